// round 6
// baseline (speedup 1.0000x reference)
#include <cuda_runtime.h>
#include <cstdint>

#define F_IN 512
#define D1   256
#define D2   64
#define CLS  16
#define MAXN 50176
#define MAXE 800000

// ---------------- scratch (device globals; no allocation allowed) ----------------
__device__ float g_H[MAXN * D1];    // GEMM output (pre-scaled by dinv[row]); reused layer1/3
__device__ float g_T1[MAXN * D1];   // h1
__device__ float g_T2b[MAXN * D1];  // h2
__device__ float g_H2a[MAXN * D2];  // x@W20 scaled
__device__ float g_T2a[MAXN * D2];  // layer2 output
__device__ float g_dinv1[MAXN];
__device__ float g_dinv2[MAXN];
__device__ int   g_cnt1[MAXN];
__device__ int   g_cnt2[MAXN];
__device__ int   g_offs1[MAXN + 1];
__device__ int   g_offs2[MAXN + 1];
__device__ int   g_cur1[MAXN];
__device__ int   g_cur2[MAXN];
__device__ int   g_csr1[MAXE];
__device__ int   g_csr2[MAXE];

// ---------------- CSR build ----------------
__global__ void zero_cnt(int* __restrict__ c1, int* __restrict__ c2, int n) {
    int i = blockIdx.x * blockDim.x + threadIdx.x;
    if (i < n) { c1[i] = 0; c2[i] = 0; }
}

__global__ void hist_kernel(const int* __restrict__ e1, const int* __restrict__ e2,
                            int* __restrict__ c1, int* __restrict__ c2, int E1, int E2) {
    int i = blockIdx.x * blockDim.x + threadIdx.x;
    if (i < E1) atomicAdd(c1 + e1[E1 + i], 1);
    if (i < E2) atomicAdd(c2 + e2[E2 + i], 1);
}

// single block, 1024 threads: exclusive prefix sum of cnt -> offs & cursor; dinv = rsqrt(cnt+1)
__global__ void scan_kernel(const int* __restrict__ cnt, int* __restrict__ offs,
                            int* __restrict__ cursor, float* __restrict__ dinv, int n) {
    __shared__ int part[1024];
    int t = threadIdx.x;
    int chunk = (n + 1023) >> 10;
    int lo = t * chunk;
    int hi = lo + chunk; if (hi > n) hi = n;
    if (lo > n) lo = n;
    int s = 0;
    for (int i = lo; i < hi; i++) s += cnt[i];
    part[t] = s;
    __syncthreads();
    for (int d = 1; d < 1024; d <<= 1) {
        int v = (t >= d) ? part[t - d] : 0;
        __syncthreads();
        part[t] += v;
        __syncthreads();
    }
    if (t == 0) offs[n] = part[1023];
    int base = (t == 0) ? 0 : part[t - 1];
    for (int i = lo; i < hi; i++) {
        int c = cnt[i];
        offs[i] = base;
        cursor[i] = base;
        dinv[i] = rsqrtf((float)c + 1.0f);
        base += c;
    }
}

__global__ void fill_csr(const int* __restrict__ e, int* __restrict__ cursor,
                         int* __restrict__ csr, int E) {
    int i = blockIdx.x * blockDim.x + threadIdx.x;
    if (i >= E) return;
    int src = e[i];
    int dst = e[E + i];
    int pos = atomicAdd(cursor + dst, 1);
    csr[pos] = src;
}

// ---------------- SGEMM (scalar, round-1 scheme) + dinv row-scale at store ----------------
// BM=128, BN=64, BK=16, 256 threads, 8x4 per thread.
__global__ void sgemm_kernel(const float* __restrict__ A, const float* __restrict__ B,
                             float* __restrict__ C, const float* __restrict__ dinv,
                             int M, int N, int K)
{
    __shared__ __align__(16) float As[16][128];
    __shared__ __align__(16) float Bs[16][64];

    const int tid = threadIdx.x;
    const int tx = tid & 15;
    const int ty = tid >> 4;

    const int block_row = blockIdx.y * 128;
    const int block_col = blockIdx.x * 64;

    const int a_row = tid >> 2;
    const int a_k4  = (tid & 3) * 4;
    const int b_k   = tid >> 4;
    const int b_n4  = (tid & 15) * 4;

    float acc[8][4];
    #pragma unroll
    for (int i = 0; i < 8; i++)
        #pragma unroll
        for (int j = 0; j < 4; j++) acc[i][j] = 0.f;

    for (int k0 = 0; k0 < K; k0 += 16) {
        #pragma unroll
        for (int h = 0; h < 2; h++) {
            int r  = a_row + h * 64;
            int gr = block_row + r;
            float4 v = (gr < M) ? *(const float4*)(A + (size_t)gr * K + k0 + a_k4)
                                : make_float4(0.f, 0.f, 0.f, 0.f);
            As[a_k4 + 0][r] = v.x;
            As[a_k4 + 1][r] = v.y;
            As[a_k4 + 2][r] = v.z;
            As[a_k4 + 3][r] = v.w;
        }
        float4 bv = *(const float4*)(B + (size_t)(k0 + b_k) * N + block_col + b_n4);
        *(float4*)&Bs[b_k][b_n4] = bv;
        __syncthreads();

        #pragma unroll
        for (int k = 0; k < 16; k++) {
            float4 a0 = *(const float4*)&As[k][ty * 8];
            float4 a1 = *(const float4*)&As[k][ty * 8 + 4];
            float4 bq = *(const float4*)&Bs[k][tx * 4];
            float a[8] = {a0.x, a0.y, a0.z, a0.w, a1.x, a1.y, a1.z, a1.w};
            float b[4] = {bq.x, bq.y, bq.z, bq.w};
            #pragma unroll
            for (int i = 0; i < 8; i++)
                #pragma unroll
                for (int j = 0; j < 4; j++)
                    acc[i][j] = fmaf(a[i], b[j], acc[i][j]);
        }
        __syncthreads();
    }

    #pragma unroll
    for (int i = 0; i < 8; i++) {
        int row = block_row + ty * 8 + i;
        if (row < M) {
            float dv = dinv[row];
            float4 v = make_float4(acc[i][0] * dv, acc[i][1] * dv,
                                   acc[i][2] * dv, acc[i][3] * dv);
            *(float4*)(C + (size_t)row * N + block_col + tx * 4) = v;
        }
    }
}

// ---------------- CSR aggregation (fused GCN propagate + self-loop + bias + relu) ----------------
// out[w] = maybe_relu( (sum_{s in N(w)} Hs[s] + Hs[w]) * dinv[w] + b )
// Hs rows are pre-scaled by dinv[src] (done in GEMM store).
template<bool RELU>
__global__ void agg_d256(const float* __restrict__ Hs, float* __restrict__ T,
                         const int* __restrict__ offs, const int* __restrict__ csr,
                         const float* __restrict__ dinv, const float* __restrict__ b, int n)
{
    int w = (blockIdx.x * blockDim.x + threadIdx.x) >> 5;
    if (w >= n) return;
    int lane = threadIdx.x & 31;
    int beg = offs[w], end = offs[w + 1];

    const float4* sp = (const float4*)(Hs + (size_t)w * 256);
    float4 a0 = sp[lane];
    float4 a1 = sp[lane + 32];

    int j = beg;
    for (; j + 1 < end; j += 2) {
        int s0 = __ldg(csr + j);
        int s1 = __ldg(csr + j + 1);
        const float4* p0 = (const float4*)(Hs + (size_t)s0 * 256);
        const float4* p1 = (const float4*)(Hs + (size_t)s1 * 256);
        float4 v00 = p0[lane], v01 = p0[lane + 32];
        float4 v10 = p1[lane], v11 = p1[lane + 32];
        a0.x += v00.x + v10.x; a0.y += v00.y + v10.y;
        a0.z += v00.z + v10.z; a0.w += v00.w + v10.w;
        a1.x += v01.x + v11.x; a1.y += v01.y + v11.y;
        a1.z += v01.z + v11.z; a1.w += v01.w + v11.w;
    }
    if (j < end) {
        int s0 = __ldg(csr + j);
        const float4* p0 = (const float4*)(Hs + (size_t)s0 * 256);
        float4 v00 = p0[lane], v01 = p0[lane + 32];
        a0.x += v00.x; a0.y += v00.y; a0.z += v00.z; a0.w += v00.w;
        a1.x += v01.x; a1.y += v01.y; a1.z += v01.z; a1.w += v01.w;
    }

    float dv = dinv[w];
    float4 b0 = *(const float4*)(b + lane * 4);
    float4 b1 = *(const float4*)(b + 128 + lane * 4);
    float4 r0, r1;
    r0.x = fmaf(a0.x, dv, b0.x); r0.y = fmaf(a0.y, dv, b0.y);
    r0.z = fmaf(a0.z, dv, b0.z); r0.w = fmaf(a0.w, dv, b0.w);
    r1.x = fmaf(a1.x, dv, b1.x); r1.y = fmaf(a1.y, dv, b1.y);
    r1.z = fmaf(a1.z, dv, b1.z); r1.w = fmaf(a1.w, dv, b1.w);
    if (RELU) {
        r0.x = fmaxf(r0.x, 0.f); r0.y = fmaxf(r0.y, 0.f);
        r0.z = fmaxf(r0.z, 0.f); r0.w = fmaxf(r0.w, 0.f);
        r1.x = fmaxf(r1.x, 0.f); r1.y = fmaxf(r1.y, 0.f);
        r1.z = fmaxf(r1.z, 0.f); r1.w = fmaxf(r1.w, 0.f);
    }
    float4* tp = (float4*)(T + (size_t)w * 256);
    tp[lane] = r0;
    tp[lane + 32] = r1;
}

template<bool RELU>
__global__ void agg_d64(const float* __restrict__ Hs, float* __restrict__ T,
                        const int* __restrict__ offs, const int* __restrict__ csr,
                        const float* __restrict__ dinv, const float* __restrict__ b, int n)
{
    int w = (blockIdx.x * blockDim.x + threadIdx.x) >> 5;
    if (w >= n) return;
    int lane = threadIdx.x & 31;
    int beg = offs[w], end = offs[w + 1];

    const float2* sp = (const float2*)(Hs + (size_t)w * 64);
    float2 a = sp[lane];

    int j = beg;
    for (; j + 3 < end; j += 4) {
        int s0 = __ldg(csr + j), s1 = __ldg(csr + j + 1);
        int s2 = __ldg(csr + j + 2), s3 = __ldg(csr + j + 3);
        float2 v0 = ((const float2*)(Hs + (size_t)s0 * 64))[lane];
        float2 v1 = ((const float2*)(Hs + (size_t)s1 * 64))[lane];
        float2 v2 = ((const float2*)(Hs + (size_t)s2 * 64))[lane];
        float2 v3 = ((const float2*)(Hs + (size_t)s3 * 64))[lane];
        a.x += (v0.x + v1.x) + (v2.x + v3.x);
        a.y += (v0.y + v1.y) + (v2.y + v3.y);
    }
    for (; j < end; j++) {
        int s0 = __ldg(csr + j);
        float2 v0 = ((const float2*)(Hs + (size_t)s0 * 64))[lane];
        a.x += v0.x; a.y += v0.y;
    }

    float dv = dinv[w];
    float2 bb = *(const float2*)(b + lane * 2);
    float2 r;
    r.x = fmaf(a.x, dv, bb.x);
    r.y = fmaf(a.y, dv, bb.y);
    if (RELU) { r.x = fmaxf(r.x, 0.f); r.y = fmaxf(r.y, 0.f); }
    ((float2*)(T + (size_t)w * 64))[lane] = r;
}

// ---------------- final: out = (A1 + A2) @ Wfc + bfc ----------------
__global__ void final_fc(const float* __restrict__ A1, const float* __restrict__ A2,
                         const float* __restrict__ W, const float* __restrict__ b,
                         float* __restrict__ out, int n)
{
    __shared__ float Ws[D1][17];
    __shared__ float bs[CLS];
    for (int i = threadIdx.x; i < D1 * CLS; i += blockDim.x)
        Ws[i >> 4][i & 15] = W[i];
    if (threadIdx.x < CLS) bs[threadIdx.x] = b[threadIdx.x];
    __syncthreads();

    int warp = threadIdx.x >> 5;
    int lane = threadIdx.x & 31;
    int row = blockIdx.x * (blockDim.x >> 5) + warp;
    if (row >= n) return;

    float acc[CLS];
    #pragma unroll
    for (int c = 0; c < CLS; c++) acc[c] = 0.f;

    const float* r1 = A1 + (size_t)row * D1;
    const float* r2 = A2 + (size_t)row * D1;
    #pragma unroll
    for (int t = 0; t < D1 / 32; t++) {
        int j = lane + t * 32;
        float s = r1[j] + r2[j];
        #pragma unroll
        for (int c = 0; c < CLS; c++)
            acc[c] = fmaf(s, Ws[j][c], acc[c]);
    }
    #pragma unroll
    for (int off = 16; off; off >>= 1)
        #pragma unroll
        for (int c = 0; c < CLS; c++)
            acc[c] += __shfl_down_sync(0xffffffffu, acc[c], off);

    if (lane == 0) {
        float* o = out + (size_t)row * CLS;
        #pragma unroll
        for (int c = 0; c < CLS; c++) o[c] = acc[c] + bs[c];
    }
}

// ---------------- launch ----------------
extern "C" void kernel_launch(void* const* d_in, const int* in_sizes, int n_in,
                              void* d_out, int out_size)
{
    const float* x   = (const float*)d_in[0];
    const int*   e1  = (const int*)d_in[1];
    const int*   e2  = (const int*)d_in[2];
    const float* W10 = (const float*)d_in[3];
    const float* b10 = (const float*)d_in[4];
    const float* W20 = (const float*)d_in[5];
    const float* b20 = (const float*)d_in[6];
    const float* W21 = (const float*)d_in[7];
    const float* b21 = (const float*)d_in[8];
    const float* Wfc = (const float*)d_in[9];
    const float* bfc = (const float*)d_in[10];
    float* out = (float*)d_out;

    int n  = in_sizes[0] / F_IN;
    int E1 = in_sizes[1] / 2;
    int E2 = in_sizes[2] / 2;

    float *H, *T1, *T2b, *H2a, *T2a, *dv1, *dv2;
    int *cnt1, *cnt2, *offs1, *offs2, *cur1, *cur2, *csr1, *csr2;
    cudaGetSymbolAddress((void**)&H,    g_H);
    cudaGetSymbolAddress((void**)&T1,   g_T1);
    cudaGetSymbolAddress((void**)&T2b,  g_T2b);
    cudaGetSymbolAddress((void**)&H2a,  g_H2a);
    cudaGetSymbolAddress((void**)&T2a,  g_T2a);
    cudaGetSymbolAddress((void**)&dv1,  g_dinv1);
    cudaGetSymbolAddress((void**)&dv2,  g_dinv2);
    cudaGetSymbolAddress((void**)&cnt1, g_cnt1);
    cudaGetSymbolAddress((void**)&cnt2, g_cnt2);
    cudaGetSymbolAddress((void**)&offs1, g_offs1);
    cudaGetSymbolAddress((void**)&offs2, g_offs2);
    cudaGetSymbolAddress((void**)&cur1, g_cur1);
    cudaGetSymbolAddress((void**)&cur2, g_cur2);
    cudaGetSymbolAddress((void**)&csr1, g_csr1);
    cudaGetSymbolAddress((void**)&csr2, g_csr2);

    const int tb = 256;
    int Emax = E1 > E2 ? E1 : E2;
    dim3 g256(D1 / 64, (n + 127) / 128);
    dim3 g64 (D2 / 64, (n + 127) / 128);
    int aggBlocks = ((size_t)n * 32 + tb - 1) / tb;

    // ---- launch order chosen so launch index 5 (ncu -s 5 -c 1) = agg_d256 layer1 ----
    zero_cnt<<<(n + tb - 1) / tb, tb>>>(cnt1, cnt2, n);                      // 0
    hist_kernel<<<(Emax + tb - 1) / tb, tb>>>(e1, e2, cnt1, cnt2, E1, E2);   // 1
    scan_kernel<<<1, 1024>>>(cnt1, offs1, cur1, dv1, n);                     // 2
    sgemm_kernel<<<g256, tb>>>(x, W10, H, dv1, n, D1, F_IN);                 // 3
    fill_csr<<<(E1 + tb - 1) / tb, tb>>>(e1, cur1, csr1, E1);                // 4
    agg_d256<true><<<aggBlocks, tb>>>(H, T1, offs1, csr1, dv1, b10, n);      // 5  <- profiled

    scan_kernel<<<1, 1024>>>(cnt2, offs2, cur2, dv2, n);                     // 6
    fill_csr<<<(E2 + tb - 1) / tb, tb>>>(e2, cur2, csr2, E2);                // 7
    sgemm_kernel<<<g64, tb>>>(x, W20, H2a, dv2, n, D2, F_IN);                // 8
    agg_d64<false><<<aggBlocks, tb>>>(H2a, T2a, offs2, csr2, dv2, b20, n);   // 9

    sgemm_kernel<<<g256, tb>>>(T2a, W21, H, dv2, n, D1, D2);                 // 10
    agg_d256<true><<<aggBlocks, tb>>>(H, T2b, offs2, csr2, dv2, b21, n);     // 11

    final_fc<<<(n + 7) / 8, tb>>>(T1, T2b, Wfc, bfc, out, n);                // 12
}

// round 8
// speedup vs baseline: 1.7765x; 1.7765x over previous
#include <cuda_runtime.h>
#include <cuda_bf16.h>
#include <cstdint>

typedef __nv_bfloat16 bf16;

#define F_IN 512
#define D1   256
#define D2   64
#define CLS  16
#define MAXN 50176

// ---------------- scratch (device globals; no allocation allowed) ----------------
__device__ float g_H[MAXN * D1];     // GEMM output, pre-scaled by dinv[row]
__device__ float g_T1[MAXN * D1];    // h1
__device__ float g_T2b[MAXN * D1];   // h2
__device__ float g_H2a[MAXN * D2];   // (x@W20)*dinv2
__device__ float g_T2a[MAXN * D2];   // layer2 scatter target
__device__ float g_deg1[MAXN];
__device__ float g_deg2[MAXN];
__device__ bf16  g_xhi[MAXN * F_IN];
__device__ bf16  g_xlo[MAXN * F_IN];
__device__ bf16  g_w10h[D1 * F_IN];
__device__ bf16  g_w10l[D1 * F_IN];
__device__ bf16  g_w20h[D2 * F_IN];
__device__ bf16  g_w20l[D2 * F_IN];
__device__ bf16  g_w21h[D1 * D2];
__device__ bf16  g_w21l[D1 * D2];
__device__ bf16  g_h2ah[MAXN * D2];
__device__ bf16  g_h2al[MAXN * D2];

// ================= helpers =================
__device__ __forceinline__ uint32_t smem_u32(const void* p) {
    uint32_t a;
    asm("{ .reg .u64 t; cvta.to.shared.u64 t, %1; cvt.u32.u64 %0, t; }" : "=r"(a) : "l"(p));
    return a;
}

#define LDM_X4(r, a)                                                              \
    asm volatile("ldmatrix.sync.aligned.m8n8.x4.shared.b16 {%0,%1,%2,%3}, [%4];"  \
        : "=r"((r)[0]), "=r"((r)[1]), "=r"((r)[2]), "=r"((r)[3]) : "r"(a))
#define LDM_X2(r, a)                                                              \
    asm volatile("ldmatrix.sync.aligned.m8n8.x2.shared.b16 {%0,%1}, [%2];"        \
        : "=r"((r)[0]), "=r"((r)[1]) : "r"(a))

__device__ __forceinline__ void mma16816(float* c, const uint32_t* a, const uint32_t* b) {
    asm volatile(
        "mma.sync.aligned.m16n8k16.row.col.f32.bf16.bf16.f32 "
        "{%0,%1,%2,%3}, {%4,%5,%6,%7}, {%8,%9}, {%0,%1,%2,%3};"
        : "+f"(c[0]), "+f"(c[1]), "+f"(c[2]), "+f"(c[3])
        : "r"(a[0]), "r"(a[1]), "r"(a[2]), "r"(a[3]), "r"(b[0]), "r"(b[1]));
}

// ================= utility kernels =================
__global__ void zero_kernel(float4* __restrict__ p, int n4) {
    int i = blockIdx.x * blockDim.x + threadIdx.x;
    if (i < n4) p[i] = make_float4(0.f, 0.f, 0.f, 0.f);
}
__global__ void deg_init(float* __restrict__ d1, float* __restrict__ d2, int n) {
    int i = blockIdx.x * blockDim.x + threadIdx.x;
    if (i < n) { d1[i] = 1.0f; d2[i] = 1.0f; }
}
__global__ void deg_count(const int* __restrict__ e1, const int* __restrict__ e2,
                          float* __restrict__ d1, float* __restrict__ d2, int E1, int E2) {
    int i = blockIdx.x * blockDim.x + threadIdx.x;
    if (i < E1) atomicAdd(d1 + e1[E1 + i], 1.0f);
    if (i < E2) atomicAdd(d2 + e2[E2 + i], 1.0f);
}
__global__ void deg_finish(float* __restrict__ d1, float* __restrict__ d2, int n) {
    int i = blockIdx.x * blockDim.x + threadIdx.x;
    if (i < n) { d1[i] = rsqrtf(d1[i]); d2[i] = rsqrtf(d2[i]); }
}

// split fp32 -> bf16 hi/lo
__device__ __forceinline__ void split_bf16(float v, unsigned short& h, unsigned short& l) {
    bf16 hb = __float2bfloat16_rn(v);
    bf16 lb = __float2bfloat16_rn(v - __bfloat162float(hb));
    h = __bfloat16_as_ushort(hb);
    l = __bfloat16_as_ushort(lb);
}

__global__ void convert_x(const float4* __restrict__ x, uint2* __restrict__ xh,
                          uint2* __restrict__ xl, int total4) {
    int i = blockIdx.x * blockDim.x + threadIdx.x;
    if (i >= total4) return;
    float4 v = x[i];
    unsigned short h0, l0, h1, l1, h2, l2, h3, l3;
    split_bf16(v.x, h0, l0); split_bf16(v.y, h1, l1);
    split_bf16(v.z, h2, l2); split_bf16(v.w, h3, l3);
    uint2 uh, ul;
    uh.x = (uint32_t)h0 | ((uint32_t)h1 << 16);
    uh.y = (uint32_t)h2 | ((uint32_t)h3 << 16);
    ul.x = (uint32_t)l0 | ((uint32_t)l1 << 16);
    ul.y = (uint32_t)l2 | ((uint32_t)l3 << 16);
    xh[i] = uh; xl[i] = ul;
}

// transpose + split weights: W[K,N] -> Wt[N,K] bf16 hi/lo
__global__ void convert_w(const float* __restrict__ W10, const float* __restrict__ W20,
                          const float* __restrict__ W21,
                          bf16* __restrict__ w10h, bf16* __restrict__ w10l,
                          bf16* __restrict__ w20h, bf16* __restrict__ w20l,
                          bf16* __restrict__ w21h, bf16* __restrict__ w21l) {
    int i = blockIdx.x * blockDim.x + threadIdx.x;
    float v; bf16 *ph, *pl; int oi;
    if (i < 131072)      { int k = i >> 8, nn = i & 255; v = W10[i]; ph = w10h; pl = w10l; oi = nn * 512 + k; }
    else if (i < 163840) { int j = i - 131072; int k = j >> 6, nn = j & 63;  v = W20[j]; ph = w20h; pl = w20l; oi = nn * 512 + k; }
    else if (i < 180224) { int j = i - 163840; int k = j >> 8, nn = j & 255; v = W21[j]; ph = w21h; pl = w21l; oi = nn * 64 + k; }
    else return;
    unsigned short h, l;
    split_bf16(v, h, l);
    ph[oi] = __ushort_as_bfloat16(h);
    pl[oi] = __ushort_as_bfloat16(l);
}

// ================= bf16-split GEMM via mma.sync (HMMA) =================
// C[M,N] = (Ahi+Alo)[M,K] @ (Bhi+Blo)[N,K]^T * dinv[row]   (lo*lo dropped)
// BM=128, BN template (128 or 64), BK=64, 256 threads = 8 warps (2x4),
// warp tile 64 x (BN/4). Smem rows padded to 72 bf16 (144B) -> conflict-free ldmatrix.
template<int BN>
__global__ void __launch_bounds__(256, 1)
gemm_mma(const bf16* __restrict__ Ahi, const bf16* __restrict__ Alo,
         const bf16* __restrict__ Bhi, const bf16* __restrict__ Blo,
         float* __restrict__ C, const float* __restrict__ dinv,
         int M, int N, int K)
{
    constexpr int LD = 72;                    // padded row length (elems) for BK=64
    constexpr int WN = BN / 4;                // warp n-tile
    constexpr int NFR = WN / 8;               // n fragments per warp
    constexpr int ABYTES = 128 * LD * 2;      // one A term
    constexpr int BBYTES = BN * LD * 2;       // one B term

    extern __shared__ char smem[];
    bf16* sAh = (bf16*)smem;
    bf16* sAl = sAh + 128 * LD;
    bf16* sBh = sAl + 128 * LD;
    bf16* sBl = sBh + BN * LD;

    const int tid  = threadIdx.x;
    const int wid  = tid >> 5;
    const int lane = tid & 31;
    const int wr = wid >> 2;                  // 0..1 : warp row (64 rows each)
    const int wc = wid & 3;                   // 0..3 : warp col (WN cols each)
    const int block_row = blockIdx.y * 128;
    const int block_col = blockIdx.x * BN;

    const uint32_t sb = smem_u32(smem);
    const int a_r = lane & 15;                // ldmatrix x4 lane->row
    const int a_k = (lane >> 4) << 3;         // lanes 16-31 -> k+8
    const int b_r = lane & 7;                 // ldmatrix x2 lane->row (lanes 0-15 used)
    const int b_k = ((lane >> 3) & 1) << 3;

    float acc[4][NFR][4];
    #pragma unroll
    for (int mi = 0; mi < 4; mi++)
        #pragma unroll
        for (int ni = 0; ni < NFR; ni++)
            #pragma unroll
            for (int q = 0; q < 4; q++) acc[mi][ni][q] = 0.f;

    const int nch = K >> 6;
    for (int ch = 0; ch < nch; ch++) {
        const int k0 = ch << 6;
        // ---- load A tiles (128 x 64 bf16, hi+lo) ----
        #pragma unroll
        for (int t = 0; t < 4; t++) {
            int idx = tid + t * 256;          // 1024 uint4 slots
            int r = idx >> 3, c8 = (idx & 7) * 8;
            int gr = block_row + r;
            uint4 vh = make_uint4(0, 0, 0, 0), vl = make_uint4(0, 0, 0, 0);
            if (gr < M) {
                vh = *(const uint4*)(Ahi + (size_t)gr * K + k0 + c8);
                vl = *(const uint4*)(Alo + (size_t)gr * K + k0 + c8);
            }
            *(uint4*)(sAh + r * LD + c8) = vh;
            *(uint4*)(sAl + r * LD + c8) = vl;
        }
        // ---- load B tiles (BN x 64 bf16, hi+lo) ----
        #pragma unroll
        for (int t = 0; t < BN / 32; t++) {
            int idx = tid + t * 256;
            int r = idx >> 3, c8 = (idx & 7) * 8;
            const bf16* bh = Bhi + (size_t)(block_col + r) * K + k0 + c8;
            const bf16* bl = Blo + (size_t)(block_col + r) * K + k0 + c8;
            *(uint4*)(sBh + r * LD + c8) = *(const uint4*)bh;
            *(uint4*)(sBl + r * LD + c8) = *(const uint4*)bl;
        }
        __syncthreads();

        #pragma unroll
        for (int ks = 0; ks < 4; ks++) {
            uint32_t ah[4][4], al[4][4];
            #pragma unroll
            for (int mi = 0; mi < 4; mi++) {
                uint32_t ad = sb + (uint32_t)(((wr * 64 + mi * 16 + a_r) * LD + ks * 16 + a_k) * 2);
                LDM_X4(ah[mi], ad);
                LDM_X4(al[mi], ad + ABYTES);
            }
            #pragma unroll
            for (int ni = 0; ni < NFR; ni++) {
                uint32_t bd = sb + (uint32_t)(2 * ABYTES + ((wc * WN + ni * 8 + b_r) * LD + ks * 16 + b_k) * 2);
                uint32_t bh[2], bl[2];
                LDM_X2(bh, bd);
                LDM_X2(bl, bd + BBYTES);
                #pragma unroll
                for (int mi = 0; mi < 4; mi++) {
                    mma16816(acc[mi][ni], ah[mi], bh);
                    mma16816(acc[mi][ni], ah[mi], bl);
                    mma16816(acc[mi][ni], al[mi], bh);
                }
            }
        }
        __syncthreads();
    }

    // ---- epilogue: scale rows by dinv, store fp32 ----
    const int tq = lane >> 2;          // row within 8
    const int tr = (lane & 3) * 2;     // col pair
    #pragma unroll
    for (int mi = 0; mi < 4; mi++) {
        int r0 = block_row + wr * 64 + mi * 16 + tq;
        int r1 = r0 + 8;
        float dv0 = (r0 < M) ? dinv[r0] : 0.f;
        float dv1 = (r1 < M) ? dinv[r1] : 0.f;
        #pragma unroll
        for (int ni = 0; ni < NFR; ni++) {
            int cc = block_col + wc * WN + ni * 8 + tr;
            if (r0 < M) {
                float2 v = make_float2(acc[mi][ni][0] * dv0, acc[mi][ni][1] * dv0);
                *(float2*)(C + (size_t)r0 * N + cc) = v;
            }
            if (r1 < M) {
                float2 v = make_float2(acc[mi][ni][2] * dv1, acc[mi][ni][3] * dv1);
                *(float2*)(C + (size_t)r1 * N + cc) = v;
            }
        }
    }
}

// ================= edge scatter: T[dst] += H'[src] (rows pre-scaled) =================
__device__ __forceinline__ void red_add4(float* p, float4 v) {
    asm volatile("red.global.add.v4.f32 [%0], {%1,%2,%3,%4};"
                 :: "l"(p), "f"(v.x), "f"(v.y), "f"(v.z), "f"(v.w) : "memory");
}
__device__ __forceinline__ void red_add2(float* p, float x, float y) {
    asm volatile("red.global.add.v2.f32 [%0], {%1,%2};"
                 :: "l"(p), "f"(x), "f"(y) : "memory");
}

__global__ void scatter_d256(const float* __restrict__ H, float* __restrict__ T,
                             const int* __restrict__ ei, int E) {
    int w = (blockIdx.x * blockDim.x + threadIdx.x) >> 5;
    if (w >= E) return;
    int lane = threadIdx.x & 31;
    int src = ei[w];
    int dst = ei[E + w];
    const float4* hs = (const float4*)(H + (size_t)src * 256);
    float* tp = T + (size_t)dst * 256;
    red_add4(tp + lane * 4, hs[lane]);
    red_add4(tp + 128 + lane * 4, hs[lane + 32]);
}

__global__ void scatter_d64(const float* __restrict__ H, float* __restrict__ T,
                            const int* __restrict__ ei, int E) {
    int w = (blockIdx.x * blockDim.x + threadIdx.x) >> 5;
    if (w >= E) return;
    int lane = threadIdx.x & 31;
    int src = ei[w];
    int dst = ei[E + w];
    float2 v = ((const float2*)(H + (size_t)src * 64))[lane];
    red_add2(T + (size_t)dst * 64 + lane * 2, v.x, v.y);
}

// ================= epilogues: out = maybe_relu((T + H')*dinv + b) =================
__global__ void epi_d256(float* __restrict__ T, const float* __restrict__ H,
                         const float* __restrict__ dinv, const float* __restrict__ b,
                         int n, int do_relu) {
    int idx = blockIdx.x * blockDim.x + threadIdx.x;
    if (idx >= n * 64) return;
    int i = idx >> 6;
    int j4 = (idx & 63) << 2;
    float dv = dinv[i];
    size_t off = (size_t)i * 256 + j4;
    float4 t = *(float4*)(T + off);
    float4 h = *(const float4*)(H + off);
    float4 bb = *(const float4*)(b + j4);
    float4 r;
    r.x = fmaf(t.x + h.x, dv, bb.x);
    r.y = fmaf(t.y + h.y, dv, bb.y);
    r.z = fmaf(t.z + h.z, dv, bb.z);
    r.w = fmaf(t.w + h.w, dv, bb.w);
    if (do_relu) {
        r.x = fmaxf(r.x, 0.f); r.y = fmaxf(r.y, 0.f);
        r.z = fmaxf(r.z, 0.f); r.w = fmaxf(r.w, 0.f);
    }
    *(float4*)(T + off) = r;
}

// layer-2 epilogue: h2a (no relu), emitted directly as bf16 hi/lo for GEMM3
__global__ void epi_d64_emit(const float* __restrict__ T, const float* __restrict__ H,
                             const float* __restrict__ dinv, const float* __restrict__ b,
                             uint2* __restrict__ ah, uint2* __restrict__ al, int n) {
    int idx = blockIdx.x * blockDim.x + threadIdx.x;
    if (idx >= n * 16) return;
    int i = idx >> 4;
    int j4 = (idx & 15) << 2;
    float dv = dinv[i];
    size_t off = (size_t)i * 64 + j4;
    float4 t = *(const float4*)(T + off);
    float4 h = *(const float4*)(H + off);
    float4 bb = *(const float4*)(b + j4);
    float4 r;
    r.x = fmaf(t.x + h.x, dv, bb.x);
    r.y = fmaf(t.y + h.y, dv, bb.y);
    r.z = fmaf(t.z + h.z, dv, bb.z);
    r.w = fmaf(t.w + h.w, dv, bb.w);
    unsigned short h0, l0, h1, l1, h2, l2, h3, l3;
    split_bf16(r.x, h0, l0); split_bf16(r.y, h1, l1);
    split_bf16(r.z, h2, l2); split_bf16(r.w, h3, l3);
    uint2 uh, ul;
    uh.x = (uint32_t)h0 | ((uint32_t)h1 << 16);
    uh.y = (uint32_t)h2 | ((uint32_t)h3 << 16);
    ul.x = (uint32_t)l0 | ((uint32_t)l1 << 16);
    ul.y = (uint32_t)l2 | ((uint32_t)l3 << 16);
    ah[idx] = uh; al[idx] = ul;
}

// ================= final: out = (A1 + A2) @ Wfc + bfc =================
__global__ void final_fc(const float* __restrict__ A1, const float* __restrict__ A2,
                         const float* __restrict__ W, const float* __restrict__ b,
                         float* __restrict__ out, int n) {
    __shared__ float Ws[D1][17];
    __shared__ float bs[CLS];
    for (int i = threadIdx.x; i < D1 * CLS; i += blockDim.x)
        Ws[i >> 4][i & 15] = W[i];
    if (threadIdx.x < CLS) bs[threadIdx.x] = b[threadIdx.x];
    __syncthreads();

    int warp = threadIdx.x >> 5;
    int lane = threadIdx.x & 31;
    int row = blockIdx.x * (blockDim.x >> 5) + warp;
    if (row >= n) return;

    float acc[CLS];
    #pragma unroll
    for (int c = 0; c < CLS; c++) acc[c] = 0.f;

    const float* r1 = A1 + (size_t)row * D1;
    const float* r2 = A2 + (size_t)row * D1;
    #pragma unroll
    for (int t = 0; t < D1 / 32; t++) {
        int j = lane + t * 32;
        float s = r1[j] + r2[j];
        #pragma unroll
        for (int c = 0; c < CLS; c++)
            acc[c] = fmaf(s, Ws[j][c], acc[c]);
    }
    #pragma unroll
    for (int off = 16; off; off >>= 1)
        #pragma unroll
        for (int c = 0; c < CLS; c++)
            acc[c] += __shfl_down_sync(0xffffffffu, acc[c], off);

    if (lane == 0) {
        float* o = out + (size_t)row * CLS;
        #pragma unroll
        for (int c = 0; c < CLS; c++) o[c] = acc[c] + bs[c];
    }
}

// ================= launch =================
extern "C" void kernel_launch(void* const* d_in, const int* in_sizes, int n_in,
                              void* d_out, int out_size)
{
    const float* x   = (const float*)d_in[0];
    const int*   e1  = (const int*)d_in[1];
    const int*   e2  = (const int*)d_in[2];
    const float* W10 = (const float*)d_in[3];
    const float* b10 = (const float*)d_in[4];
    const float* W20 = (const float*)d_in[5];
    const float* b20 = (const float*)d_in[6];
    const float* W21 = (const float*)d_in[7];
    const float* b21 = (const float*)d_in[8];
    const float* Wfc = (const float*)d_in[9];
    const float* bfc = (const float*)d_in[10];
    float* out = (float*)d_out;

    int n  = in_sizes[0] / F_IN;
    int E1 = in_sizes[1] / 2;
    int E2 = in_sizes[2] / 2;

    float *H, *T1, *T2b, *H2a, *T2a, *dv1, *dv2;
    bf16 *xh, *xl, *w10h, *w10l, *w20h, *w20l, *w21h, *w21l, *h2ah, *h2al;
    cudaGetSymbolAddress((void**)&H,    g_H);
    cudaGetSymbolAddress((void**)&T1,   g_T1);
    cudaGetSymbolAddress((void**)&T2b,  g_T2b);
    cudaGetSymbolAddress((void**)&H2a,  g_H2a);
    cudaGetSymbolAddress((void**)&T2a,  g_T2a);
    cudaGetSymbolAddress((void**)&dv1,  g_deg1);
    cudaGetSymbolAddress((void**)&dv2,  g_deg2);
    cudaGetSymbolAddress((void**)&xh,   g_xhi);
    cudaGetSymbolAddress((void**)&xl,   g_xlo);
    cudaGetSymbolAddress((void**)&w10h, g_w10h);
    cudaGetSymbolAddress((void**)&w10l, g_w10l);
    cudaGetSymbolAddress((void**)&w20h, g_w20h);
    cudaGetSymbolAddress((void**)&w20l, g_w20l);
    cudaGetSymbolAddress((void**)&w21h, g_w21h);
    cudaGetSymbolAddress((void**)&w21l, g_w21l);
    cudaGetSymbolAddress((void**)&h2ah, g_h2ah);
    cudaGetSymbolAddress((void**)&h2al, g_h2al);

    // smem: 2 A terms (128x72) + 2 B terms (BNx72), bf16
    const int SMEM128 = (2 * 128 * 72 + 2 * 128 * 72) * 2;  // 73728
    const int SMEM64  = (2 * 128 * 72 + 2 * 64 * 72) * 2;   // 55296
    cudaFuncSetAttribute(gemm_mma<128>, cudaFuncAttributeMaxDynamicSharedMemorySize, SMEM128);
    cudaFuncSetAttribute(gemm_mma<64>,  cudaFuncAttributeMaxDynamicSharedMemorySize, SMEM64);

    const int tb = 256;
    int Emax = E1 > E2 ? E1 : E2;
    int mtiles = (n + 127) / 128;
    dim3 grid1(D1 / 128, mtiles);   // GEMM1/3: N=256
    dim3 grid2(1, mtiles);          // GEMM2:  N=64
    int scat1Blocks = (int)(((size_t)E1 * 32 + tb - 1) / tb);
    int scat2Blocks = (int)(((size_t)E2 * 32 + tb - 1) / tb);

    // 0-2: degrees -> dinv
    deg_init<<<(n + tb - 1) / tb, tb>>>(dv1, dv2, n);
    deg_count<<<(Emax + tb - 1) / tb, tb>>>(e1, e2, dv1, dv2, E1, E2);
    deg_finish<<<(n + tb - 1) / tb, tb>>>(dv1, dv2, n);

    // 3-4: bf16 split conversions
    convert_w<<<(180224 + tb - 1) / tb, tb>>>(W10, W20, W21, w10h, w10l, w20h, w20l, w21h, w21l);
    convert_x<<<(n * 128 + tb - 1) / tb, tb>>>((const float4*)x, (uint2*)xh, (uint2*)xl, n * 128);

    // 5: GEMM1 (profiled): H = (x@W10)*dinv1
    gemm_mma<128><<<grid1, tb, SMEM128>>>(xh, xl, w10h, w10l, H, dv1, n, D1, F_IN);

    // 6-8: zero scatter targets
    zero_kernel<<<(n * 64 + tb - 1) / tb, tb>>>((float4*)T1, n * 64);
    zero_kernel<<<(n * 64 + tb - 1) / tb, tb>>>((float4*)T2b, n * 64);
    zero_kernel<<<(n * 16 + tb - 1) / tb, tb>>>((float4*)T2a, n * 16);

    // 9-10: layer 1 propagate + epilogue (relu)
    scatter_d256<<<scat1Blocks, tb>>>(H, T1, e1, E1);
    epi_d256<<<(n * 64 + tb - 1) / tb, tb>>>(T1, H, dv1, b10, n, 1);

    // 11-13: layer 2: H2a = (x@W20)*dinv2 ; propagate ; epilogue emits bf16 hi/lo
    gemm_mma<64><<<grid2, tb, SMEM64>>>(xh, xl, w20h, w20l, H2a, dv2, n, D2, F_IN);
    scatter_d64<<<scat2Blocks, tb>>>(H2a, T2a, e2, E2);
    epi_d64_emit<<<(n * 16 + tb - 1) / tb, tb>>>(T2a, H2a, dv2, b20, (uint2*)h2ah, (uint2*)h2al, n);

    // 14-16: layer 3: H = (h2a@W21)*dinv2 ; propagate ; epilogue (relu)
    gemm_mma<128><<<grid1, tb, SMEM128>>>(h2ah, h2al, w21h, w21l, H, dv2, n, D1, D2);
    scatter_d256<<<scat2Blocks, tb>>>(H, T2b, e2, E2);
    epi_d256<<<(n * 64 + tb - 1) / tb, tb>>>(T2b, H, dv2, b21, n, 1);

    // 17: final dense
    final_fc<<<(n + 7) / 8, tb>>>(T1, T2b, Wfc, bfc, out, n);
}

// round 9
// speedup vs baseline: 1.8668x; 1.0508x over previous
#include <cuda_runtime.h>
#include <cuda_bf16.h>
#include <cstdint>

typedef __nv_bfloat16 bf16;

#define F_IN 512
#define D1   256
#define D2   64
#define CLS  16
#define MAXN 50176

// ---------------- scratch (device globals; no allocation allowed) ----------------
__device__ float g_H[MAXN * D1];     // GEMM output, pre-scaled by dinv[row]
__device__ float g_T1[MAXN * D1];    // h1
__device__ float g_T2b[MAXN * D1];   // h2
__device__ float g_H2a[MAXN * D2];   // (x@W20)*dinv2
__device__ float g_T2a[MAXN * D2];   // layer2 scatter target
__device__ float g_deg1[MAXN];
__device__ float g_deg2[MAXN];
__device__ bf16  g_xhi[MAXN * F_IN];
__device__ bf16  g_xlo[MAXN * F_IN];
__device__ bf16  g_w10h[D1 * F_IN];
__device__ bf16  g_w10l[D1 * F_IN];
__device__ bf16  g_w20h[D2 * F_IN];
__device__ bf16  g_w20l[D2 * F_IN];
__device__ bf16  g_w21h[D1 * D2];
__device__ bf16  g_w21l[D1 * D2];
__device__ bf16  g_h2ah[MAXN * D2];
__device__ bf16  g_h2al[MAXN * D2];

// ================= helpers =================
__device__ __forceinline__ uint32_t smem_u32(const void* p) {
    uint32_t a;
    asm("{ .reg .u64 t; cvta.to.shared.u64 t, %1; cvt.u32.u64 %0, t; }" : "=r"(a) : "l"(p));
    return a;
}

#define LDM_X4(r, a)                                                              \
    asm volatile("ldmatrix.sync.aligned.m8n8.x4.shared.b16 {%0,%1,%2,%3}, [%4];"  \
        : "=r"((r)[0]), "=r"((r)[1]), "=r"((r)[2]), "=r"((r)[3]) : "r"(a))
#define LDM_X2(r, a)                                                              \
    asm volatile("ldmatrix.sync.aligned.m8n8.x2.shared.b16 {%0,%1}, [%2];"        \
        : "=r"((r)[0]), "=r"((r)[1]) : "r"(a))

__device__ __forceinline__ void mma16816(float* c, const uint32_t* a, const uint32_t* b) {
    asm volatile(
        "mma.sync.aligned.m16n8k16.row.col.f32.bf16.bf16.f32 "
        "{%0,%1,%2,%3}, {%4,%5,%6,%7}, {%8,%9}, {%0,%1,%2,%3};"
        : "+f"(c[0]), "+f"(c[1]), "+f"(c[2]), "+f"(c[3])
        : "r"(a[0]), "r"(a[1]), "r"(a[2]), "r"(a[3]), "r"(b[0]), "r"(b[1]));
}

// cp.async 16B with zero-fill predicate (src_size = 16 or 0)
__device__ __forceinline__ void cp_async16(uint32_t dst, const void* src, int sz) {
    asm volatile("cp.async.cg.shared.global [%0], [%1], 16, %2;"
                 :: "r"(dst), "l"(src), "r"(sz));
}
#define CP_COMMIT() asm volatile("cp.async.commit_group;")
#define CP_WAIT(n)  asm volatile("cp.async.wait_group %0;" :: "n"(n))

// ================= utility kernels =================
__global__ void zero_kernel(float4* __restrict__ p, int n4) {
    int i = blockIdx.x * blockDim.x + threadIdx.x;
    if (i < n4) p[i] = make_float4(0.f, 0.f, 0.f, 0.f);
}
__global__ void deg_init(float* __restrict__ d1, float* __restrict__ d2, int n) {
    int i = blockIdx.x * blockDim.x + threadIdx.x;
    if (i < n) { d1[i] = 1.0f; d2[i] = 1.0f; }
}
__global__ void deg_count(const int* __restrict__ e1, const int* __restrict__ e2,
                          float* __restrict__ d1, float* __restrict__ d2, int E1, int E2) {
    int i = blockIdx.x * blockDim.x + threadIdx.x;
    if (i < E1) atomicAdd(d1 + e1[E1 + i], 1.0f);
    if (i < E2) atomicAdd(d2 + e2[E2 + i], 1.0f);
}
__global__ void deg_finish(float* __restrict__ d1, float* __restrict__ d2, int n) {
    int i = blockIdx.x * blockDim.x + threadIdx.x;
    if (i < n) { d1[i] = rsqrtf(d1[i]); d2[i] = rsqrtf(d2[i]); }
}

// split fp32 -> bf16 hi/lo
__device__ __forceinline__ void split_bf16(float v, unsigned short& h, unsigned short& l) {
    bf16 hb = __float2bfloat16_rn(v);
    bf16 lb = __float2bfloat16_rn(v - __bfloat162float(hb));
    h = __bfloat16_as_ushort(hb);
    l = __bfloat16_as_ushort(lb);
}

__global__ void convert_x(const float4* __restrict__ x, uint2* __restrict__ xh,
                          uint2* __restrict__ xl, int total4) {
    int i = blockIdx.x * blockDim.x + threadIdx.x;
    if (i >= total4) return;
    float4 v = x[i];
    unsigned short h0, l0, h1, l1, h2, l2, h3, l3;
    split_bf16(v.x, h0, l0); split_bf16(v.y, h1, l1);
    split_bf16(v.z, h2, l2); split_bf16(v.w, h3, l3);
    uint2 uh, ul;
    uh.x = (uint32_t)h0 | ((uint32_t)h1 << 16);
    uh.y = (uint32_t)h2 | ((uint32_t)h3 << 16);
    ul.x = (uint32_t)l0 | ((uint32_t)l1 << 16);
    ul.y = (uint32_t)l2 | ((uint32_t)l3 << 16);
    xh[i] = uh; xl[i] = ul;
}

// transpose + split weights: W[K,N] -> Wt[N,K] bf16 hi/lo
__global__ void convert_w(const float* __restrict__ W10, const float* __restrict__ W20,
                          const float* __restrict__ W21,
                          bf16* __restrict__ w10h, bf16* __restrict__ w10l,
                          bf16* __restrict__ w20h, bf16* __restrict__ w20l,
                          bf16* __restrict__ w21h, bf16* __restrict__ w21l) {
    int i = blockIdx.x * blockDim.x + threadIdx.x;
    float v; bf16 *ph, *pl; int oi;
    if (i < 131072)      { int k = i >> 8, nn = i & 255; v = W10[i]; ph = w10h; pl = w10l; oi = nn * 512 + k; }
    else if (i < 163840) { int j = i - 131072; int k = j >> 6, nn = j & 63;  v = W20[j]; ph = w20h; pl = w20l; oi = nn * 512 + k; }
    else if (i < 180224) { int j = i - 163840; int k = j >> 8, nn = j & 255; v = W21[j]; ph = w21h; pl = w21l; oi = nn * 64 + k; }
    else return;
    unsigned short h, l;
    split_bf16(v, h, l);
    ph[oi] = __ushort_as_bfloat16(h);
    pl[oi] = __ushort_as_bfloat16(l);
}

// ================= bf16-split GEMM via mma.sync + cp.async double buffer =================
// C[M,N] = (Ahi+Alo)[M,K] @ (Bhi+Blo)[N,K]^T * dinv[row]   (lo*lo dropped)
// BM=128, BN template, BK=64, 256 threads = 8 warps (2x4), warp tile 64 x (BN/4).
// Smem rows padded to 72 bf16 (144B); two pipeline stages.
template<int BN>
__global__ void __launch_bounds__(256, 1)
gemm_mma(const bf16* __restrict__ Ahi, const bf16* __restrict__ Alo,
         const bf16* __restrict__ Bhi, const bf16* __restrict__ Blo,
         float* __restrict__ C, const float* __restrict__ dinv,
         int M, int N, int K)
{
    constexpr int LD = 72;                     // padded row length (elems)
    constexpr int WN = BN / 4;                 // warp n-tile
    constexpr int NFR = WN / 8;                // n fragments per warp
    constexpr int AELEMS = 128 * LD;           // one A term (elems)
    constexpr int BELEMS = BN * LD;
    constexpr int STAGE = 2 * AELEMS + 2 * BELEMS;   // elems per stage
    constexpr int ABYTES = AELEMS * 2;
    constexpr int BBYTES = BELEMS * 2;
    constexpr int STAGEB = STAGE * 2;

    extern __shared__ bf16 smem[];             // [2 stages][Ah, Al, Bh, Bl]

    const int tid  = threadIdx.x;
    const int wid  = tid >> 5;
    const int lane = tid & 31;
    const int wr = wid >> 2;
    const int wc = wid & 3;
    const int block_row = blockIdx.y * 128;
    const int block_col = blockIdx.x * BN;

    const uint32_t sb = smem_u32(smem);

    // loader indices: A 1024 16B-slots (4 iters), B BN*8 slots (BN/32 iters)
    const int a_r0 = tid >> 3;                 // +t*32 rows? no: slot = tid + t*256
    const int a_c8 = (tid & 7) * 8;

    // ---- pipeline load of chunk ch into stage s ----
    auto load_stage = [&](int ch, int s) {
        const int k0 = ch << 6;
        uint32_t st = sb + (uint32_t)(s * STAGEB);
        #pragma unroll
        for (int t = 0; t < 4; t++) {
            int r = a_r0 + t * 32;
            int gr = block_row + r;
            int sz = (gr < M) ? 16 : 0;
            uint32_t d = st + (uint32_t)((r * LD + a_c8) * 2);
            const bf16* s1 = Ahi + (size_t)gr * K + k0 + a_c8;
            const bf16* s2 = Alo + (size_t)gr * K + k0 + a_c8;
            cp_async16(d, s1, sz);
            cp_async16(d + ABYTES, s2, sz);
        }
        #pragma unroll
        for (int t = 0; t < BN / 32; t++) {
            int r = a_r0 + t * 32;
            uint32_t d = st + (uint32_t)(2 * ABYTES + (r * LD + a_c8) * 2);
            const bf16* s1 = Bhi + (size_t)(block_col + r) * K + k0 + a_c8;
            const bf16* s2 = Blo + (size_t)(block_col + r) * K + k0 + a_c8;
            cp_async16(d, s1, 16);
            cp_async16(d + BBYTES, s2, 16);
        }
        CP_COMMIT();
    };

    const int a_r = lane & 15;
    const int a_k = (lane >> 4) << 3;
    const int b_r = lane & 7;
    const int b_k = ((lane >> 3) & 1) << 3;

    float acc[4][NFR][4];
    #pragma unroll
    for (int mi = 0; mi < 4; mi++)
        #pragma unroll
        for (int ni = 0; ni < NFR; ni++)
            #pragma unroll
            for (int q = 0; q < 4; q++) acc[mi][ni][q] = 0.f;

    const int nch = K >> 6;
    load_stage(0, 0);

    for (int ch = 0; ch < nch; ch++) {
        if (ch + 1 < nch) {
            load_stage(ch + 1, (ch + 1) & 1);
            CP_WAIT(1);
        } else {
            CP_WAIT(0);
        }
        __syncthreads();

        uint32_t st = sb + (uint32_t)((ch & 1) * STAGEB);
        #pragma unroll
        for (int ks = 0; ks < 4; ks++) {
            uint32_t ah[4][4], al[4][4];
            #pragma unroll
            for (int mi = 0; mi < 4; mi++) {
                uint32_t ad = st + (uint32_t)(((wr * 64 + mi * 16 + a_r) * LD + ks * 16 + a_k) * 2);
                LDM_X4(ah[mi], ad);
                LDM_X4(al[mi], ad + ABYTES);
            }
            #pragma unroll
            for (int ni = 0; ni < NFR; ni++) {
                uint32_t bd = st + (uint32_t)(2 * ABYTES + ((wc * WN + ni * 8 + b_r) * LD + ks * 16 + b_k) * 2);
                uint32_t bh[2], bl[2];
                LDM_X2(bh, bd);
                LDM_X2(bl, bd + BBYTES);
                #pragma unroll
                for (int mi = 0; mi < 4; mi++) {
                    mma16816(acc[mi][ni], ah[mi], bh);
                    mma16816(acc[mi][ni], ah[mi], bl);
                    mma16816(acc[mi][ni], al[mi], bh);
                }
            }
        }
        __syncthreads();
    }

    // ---- epilogue: scale rows by dinv, store fp32 ----
    const int tq = lane >> 2;
    const int tr = (lane & 3) * 2;
    #pragma unroll
    for (int mi = 0; mi < 4; mi++) {
        int r0 = block_row + wr * 64 + mi * 16 + tq;
        int r1 = r0 + 8;
        float dv0 = (r0 < M) ? dinv[r0] : 0.f;
        float dv1 = (r1 < M) ? dinv[r1] : 0.f;
        #pragma unroll
        for (int ni = 0; ni < NFR; ni++) {
            int cc = block_col + wc * WN + ni * 8 + tr;
            if (r0 < M) {
                float2 v = make_float2(acc[mi][ni][0] * dv0, acc[mi][ni][1] * dv0);
                *(float2*)(C + (size_t)r0 * N + cc) = v;
            }
            if (r1 < M) {
                float2 v = make_float2(acc[mi][ni][2] * dv1, acc[mi][ni][3] * dv1);
                *(float2*)(C + (size_t)r1 * N + cc) = v;
            }
        }
    }
}

// ================= edge scatter: T[dst] += H'[src] (rows pre-scaled) =================
__device__ __forceinline__ void red_add4(float* p, float4 v) {
    asm volatile("red.global.add.v4.f32 [%0], {%1,%2,%3,%4};"
                 :: "l"(p), "f"(v.x), "f"(v.y), "f"(v.z), "f"(v.w) : "memory");
}
__device__ __forceinline__ void red_add2(float* p, float x, float y) {
    asm volatile("red.global.add.v2.f32 [%0], {%1,%2};"
                 :: "l"(p), "f"(x), "f"(y) : "memory");
}

__global__ void scatter_d256(const float* __restrict__ H, float* __restrict__ T,
                             const int* __restrict__ ei, int E) {
    int w = (blockIdx.x * blockDim.x + threadIdx.x) >> 5;
    if (w >= E) return;
    int lane = threadIdx.x & 31;
    int src = ei[w];
    int dst = ei[E + w];
    const float4* hs = (const float4*)(H + (size_t)src * 256);
    float* tp = T + (size_t)dst * 256;
    red_add4(tp + lane * 4, hs[lane]);
    red_add4(tp + 128 + lane * 4, hs[lane + 32]);
}

__global__ void scatter_d64(const float* __restrict__ H, float* __restrict__ T,
                            const int* __restrict__ ei, int E) {
    int w = (blockIdx.x * blockDim.x + threadIdx.x) >> 5;
    if (w >= E) return;
    int lane = threadIdx.x & 31;
    int src = ei[w];
    int dst = ei[E + w];
    float2 v = ((const float2*)(H + (size_t)src * 64))[lane];
    red_add2(T + (size_t)dst * 64 + lane * 2, v.x, v.y);
}

// ================= epilogues: out = maybe_relu((T + H')*dinv + b) =================
__global__ void epi_d256(float* __restrict__ T, const float* __restrict__ H,
                         const float* __restrict__ dinv, const float* __restrict__ b,
                         int n, int do_relu) {
    int idx = blockIdx.x * blockDim.x + threadIdx.x;
    if (idx >= n * 64) return;
    int i = idx >> 6;
    int j4 = (idx & 63) << 2;
    float dv = dinv[i];
    size_t off = (size_t)i * 256 + j4;
    float4 t = *(float4*)(T + off);
    float4 h = *(const float4*)(H + off);
    float4 bb = *(const float4*)(b + j4);
    float4 r;
    r.x = fmaf(t.x + h.x, dv, bb.x);
    r.y = fmaf(t.y + h.y, dv, bb.y);
    r.z = fmaf(t.z + h.z, dv, bb.z);
    r.w = fmaf(t.w + h.w, dv, bb.w);
    if (do_relu) {
        r.x = fmaxf(r.x, 0.f); r.y = fmaxf(r.y, 0.f);
        r.z = fmaxf(r.z, 0.f); r.w = fmaxf(r.w, 0.f);
    }
    *(float4*)(T + off) = r;
}

// layer-2 epilogue: h2a (no relu), emitted directly as bf16 hi/lo for GEMM3
__global__ void epi_d64_emit(const float* __restrict__ T, const float* __restrict__ H,
                             const float* __restrict__ dinv, const float* __restrict__ b,
                             uint2* __restrict__ ah, uint2* __restrict__ al, int n) {
    int idx = blockIdx.x * blockDim.x + threadIdx.x;
    if (idx >= n * 16) return;
    int i = idx >> 4;
    int j4 = (idx & 15) << 2;
    float dv = dinv[i];
    size_t off = (size_t)i * 64 + j4;
    float4 t = *(const float4*)(T + off);
    float4 h = *(const float4*)(H + off);
    float4 bb = *(const float4*)(b + j4);
    float4 r;
    r.x = fmaf(t.x + h.x, dv, bb.x);
    r.y = fmaf(t.y + h.y, dv, bb.y);
    r.z = fmaf(t.z + h.z, dv, bb.z);
    r.w = fmaf(t.w + h.w, dv, bb.w);
    unsigned short h0, l0, h1, l1, h2, l2, h3, l3;
    split_bf16(r.x, h0, l0); split_bf16(r.y, h1, l1);
    split_bf16(r.z, h2, l2); split_bf16(r.w, h3, l3);
    uint2 uh, ul;
    uh.x = (uint32_t)h0 | ((uint32_t)h1 << 16);
    uh.y = (uint32_t)h2 | ((uint32_t)h3 << 16);
    ul.x = (uint32_t)l0 | ((uint32_t)l1 << 16);
    ul.y = (uint32_t)l2 | ((uint32_t)l3 << 16);
    ah[idx] = uh; al[idx] = ul;
}

// ================= final: out = (A1 + A2) @ Wfc + bfc =================
__global__ void final_fc(const float* __restrict__ A1, const float* __restrict__ A2,
                         const float* __restrict__ W, const float* __restrict__ b,
                         float* __restrict__ out, int n) {
    __shared__ float Ws[D1][17];
    __shared__ float bs[CLS];
    for (int i = threadIdx.x; i < D1 * CLS; i += blockDim.x)
        Ws[i >> 4][i & 15] = W[i];
    if (threadIdx.x < CLS) bs[threadIdx.x] = b[threadIdx.x];
    __syncthreads();

    int warp = threadIdx.x >> 5;
    int lane = threadIdx.x & 31;
    int row = blockIdx.x * (blockDim.x >> 5) + warp;
    if (row >= n) return;

    float acc[CLS];
    #pragma unroll
    for (int c = 0; c < CLS; c++) acc[c] = 0.f;

    const float* r1 = A1 + (size_t)row * D1;
    const float* r2 = A2 + (size_t)row * D1;
    #pragma unroll
    for (int t = 0; t < D1 / 32; t++) {
        int j = lane + t * 32;
        float s = r1[j] + r2[j];
        #pragma unroll
        for (int c = 0; c < CLS; c++)
            acc[c] = fmaf(s, Ws[j][c], acc[c]);
    }
    #pragma unroll
    for (int off = 16; off; off >>= 1)
        #pragma unroll
        for (int c = 0; c < CLS; c++)
            acc[c] += __shfl_down_sync(0xffffffffu, acc[c], off);

    if (lane == 0) {
        float* o = out + (size_t)row * CLS;
        #pragma unroll
        for (int c = 0; c < CLS; c++) o[c] = acc[c] + bs[c];
    }
}

// ================= launch =================
extern "C" void kernel_launch(void* const* d_in, const int* in_sizes, int n_in,
                              void* d_out, int out_size)
{
    const float* x   = (const float*)d_in[0];
    const int*   e1  = (const int*)d_in[1];
    const int*   e2  = (const int*)d_in[2];
    const float* W10 = (const float*)d_in[3];
    const float* b10 = (const float*)d_in[4];
    const float* W20 = (const float*)d_in[5];
    const float* b20 = (const float*)d_in[6];
    const float* W21 = (const float*)d_in[7];
    const float* b21 = (const float*)d_in[8];
    const float* Wfc = (const float*)d_in[9];
    const float* bfc = (const float*)d_in[10];
    float* out = (float*)d_out;

    int n  = in_sizes[0] / F_IN;
    int E1 = in_sizes[1] / 2;
    int E2 = in_sizes[2] / 2;

    float *H, *T1, *T2b, *H2a, *T2a, *dv1, *dv2;
    bf16 *xh, *xl, *w10h, *w10l, *w20h, *w20l, *w21h, *w21l, *h2ah, *h2al;
    cudaGetSymbolAddress((void**)&H,    g_H);
    cudaGetSymbolAddress((void**)&T1,   g_T1);
    cudaGetSymbolAddress((void**)&T2b,  g_T2b);
    cudaGetSymbolAddress((void**)&H2a,  g_H2a);
    cudaGetSymbolAddress((void**)&T2a,  g_T2a);
    cudaGetSymbolAddress((void**)&dv1,  g_deg1);
    cudaGetSymbolAddress((void**)&dv2,  g_deg2);
    cudaGetSymbolAddress((void**)&xh,   g_xhi);
    cudaGetSymbolAddress((void**)&xl,   g_xlo);
    cudaGetSymbolAddress((void**)&w10h, g_w10h);
    cudaGetSymbolAddress((void**)&w10l, g_w10l);
    cudaGetSymbolAddress((void**)&w20h, g_w20h);
    cudaGetSymbolAddress((void**)&w20l, g_w20l);
    cudaGetSymbolAddress((void**)&w21h, g_w21h);
    cudaGetSymbolAddress((void**)&w21l, g_w21l);
    cudaGetSymbolAddress((void**)&h2ah, g_h2ah);
    cudaGetSymbolAddress((void**)&h2al, g_h2al);

    // smem per stage: (2*128*72 + 2*BN*72)*2 bytes; two stages
    const int SMEM128 = 2 * (2 * 128 * 72 + 2 * 128 * 72) * 2;  // 147456
    const int SMEM64  = 2 * (2 * 128 * 72 + 2 * 64 * 72) * 2;   // 110592
    cudaFuncSetAttribute(gemm_mma<128>, cudaFuncAttributeMaxDynamicSharedMemorySize, SMEM128);
    cudaFuncSetAttribute(gemm_mma<64>,  cudaFuncAttributeMaxDynamicSharedMemorySize, SMEM64);

    const int tb = 256;
    int Emax = E1 > E2 ? E1 : E2;
    int mtiles = (n + 127) / 128;
    dim3 grid1(D1 / 128, mtiles);   // GEMM1/3: N=256
    dim3 grid2(1, mtiles);          // GEMM2:  N=64
    int scat1Blocks = (int)(((size_t)E1 * 32 + tb - 1) / tb);
    int scat2Blocks = (int)(((size_t)E2 * 32 + tb - 1) / tb);

    // 0-2: degrees -> dinv
    deg_init<<<(n + tb - 1) / tb, tb>>>(dv1, dv2, n);
    deg_count<<<(Emax + tb - 1) / tb, tb>>>(e1, e2, dv1, dv2, E1, E2);
    deg_finish<<<(n + tb - 1) / tb, tb>>>(dv1, dv2, n);

    // 3-4: bf16 split conversions
    convert_w<<<(180224 + tb - 1) / tb, tb>>>(W10, W20, W21, w10h, w10l, w20h, w20l, w21h, w21l);
    convert_x<<<(n * 128 + tb - 1) / tb, tb>>>((const float4*)x, (uint2*)xh, (uint2*)xl, n * 128);

    // 5: GEMM1 (profiled): H = (x@W10)*dinv1
    gemm_mma<128><<<grid1, tb, SMEM128>>>(xh, xl, w10h, w10l, H, dv1, n, D1, F_IN);

    // 6-8: zero scatter targets
    zero_kernel<<<(n * 64 + tb - 1) / tb, tb>>>((float4*)T1, n * 64);
    zero_kernel<<<(n * 64 + tb - 1) / tb, tb>>>((float4*)T2b, n * 64);
    zero_kernel<<<(n * 16 + tb - 1) / tb, tb>>>((float4*)T2a, n * 16);

    // 9-10: layer 1 propagate + epilogue (relu)
    scatter_d256<<<scat1Blocks, tb>>>(H, T1, e1, E1);
    epi_d256<<<(n * 64 + tb - 1) / tb, tb>>>(T1, H, dv1, b10, n, 1);

    // 11-13: layer 2: H2a = (x@W20)*dinv2 ; propagate ; epilogue emits bf16 hi/lo
    gemm_mma<64><<<grid2, tb, SMEM64>>>(xh, xl, w20h, w20l, H2a, dv2, n, D2, F_IN);
    scatter_d64<<<scat2Blocks, tb>>>(H2a, T2a, e2, E2);
    epi_d64_emit<<<(n * 16 + tb - 1) / tb, tb>>>(T2a, H2a, dv2, b20, (uint2*)h2ah, (uint2*)h2al, n);

    // 14-16: layer 3: H = (h2a@W21)*dinv2 ; propagate ; epilogue (relu)
    gemm_mma<128><<<grid1, tb, SMEM128>>>(h2ah, h2al, w21h, w21l, H, dv2, n, D1, D2);
    scatter_d256<<<scat2Blocks, tb>>>(H, T2b, e2, E2);
    epi_d256<<<(n * 64 + tb - 1) / tb, tb>>>(T2b, H, dv2, b21, n, 1);

    // 17: final dense
    final_fc<<<(n + 7) / 8, tb>>>(T1, T2b, Wfc, bfc, out, n);
}

// round 12
// speedup vs baseline: 2.1863x; 1.1711x over previous
#include <cuda_runtime.h>
#include <cuda_bf16.h>
#include <cstdint>

typedef __nv_bfloat16 bf16;

#define F_IN 512
#define D1   256
#define D2   64
#define CLS  16
#define MAXN 50176

// ---------------- scratch (device globals; no allocation allowed) ----------------
__device__ float g_H[MAXN * D1];     // GEMM1/(x@W10)*dinv1 output
__device__ float g_T1[MAXN * D1];    // layer1 scatter target -> h1
__device__ float g_T2b[MAXN * D1];   // h2 (GEMM3 output, bias+relu)
__device__ float g_H2a[MAXN * D2];   // (x@W20)*dinv2, later s = h2a*dinv2 (in place)
__device__ float g_T2a[MAXN * D2];   // layer2 scatter target
__device__ float g_T3[MAXN * D2];    // layer3 (64-dim) scatter target
__device__ float g_deg1[MAXN];       // degree counts (incl self loop)
__device__ float g_deg2[MAXN];
__device__ bf16  g_xhi[MAXN * F_IN];
__device__ bf16  g_xlo[MAXN * F_IN];
__device__ bf16  g_w10h[D1 * F_IN];
__device__ bf16  g_w10l[D1 * F_IN];
__device__ bf16  g_w20h[D2 * F_IN];
__device__ bf16  g_w20l[D2 * F_IN];
__device__ bf16  g_w21h[D1 * D2];
__device__ bf16  g_w21l[D1 * D2];
__device__ bf16  g_gh[MAXN * D2];    // G = P2(h2a) bf16 hi
__device__ bf16  g_gl[MAXN * D2];    // G bf16 lo

// ================= helpers =================
__device__ __forceinline__ uint32_t smem_u32(const void* p) {
    uint32_t a;
    asm("{ .reg .u64 t; cvta.to.shared.u64 t, %1; cvt.u32.u64 %0, t; }" : "=r"(a) : "l"(p));
    return a;
}

#define LDM_X4(r, a)                                                              \
    asm volatile("ldmatrix.sync.aligned.m8n8.x4.shared.b16 {%0,%1,%2,%3}, [%4];"  \
        : "=r"((r)[0]), "=r"((r)[1]), "=r"((r)[2]), "=r"((r)[3]) : "r"(a))
#define LDM_X2(r, a)                                                              \
    asm volatile("ldmatrix.sync.aligned.m8n8.x2.shared.b16 {%0,%1}, [%2];"        \
        : "=r"((r)[0]), "=r"((r)[1]) : "r"(a))

__device__ __forceinline__ void mma16816(float* c, const uint32_t* a, const uint32_t* b) {
    asm volatile(
        "mma.sync.aligned.m16n8k16.row.col.f32.bf16.bf16.f32 "
        "{%0,%1,%2,%3}, {%4,%5,%6,%7}, {%8,%9}, {%0,%1,%2,%3};"
        : "+f"(c[0]), "+f"(c[1]), "+f"(c[2]), "+f"(c[3])
        : "r"(a[0]), "r"(a[1]), "r"(a[2]), "r"(a[3]), "r"(b[0]), "r"(b[1]));
}

__device__ __forceinline__ void cp_async16(uint32_t dst, const void* src, int sz) {
    asm volatile("cp.async.cg.shared.global [%0], [%1], 16, %2;"
                 :: "r"(dst), "l"(src), "r"(sz));
}
#define CP_COMMIT() asm volatile("cp.async.commit_group;")
#define CP_WAIT(n)  asm volatile("cp.async.wait_group %0;" :: "n"(n))

// ================= degree kernels =================
__global__ void deg_init(float* __restrict__ d1, float* __restrict__ d2, int n) {
    int i = blockIdx.x * blockDim.x + threadIdx.x;
    if (i < n) { d1[i] = 1.0f; d2[i] = 1.0f; }
}
__global__ void deg_count(const int* __restrict__ e1, const int* __restrict__ e2,
                          float* __restrict__ d1, float* __restrict__ d2, int E1, int E2) {
    int i = blockIdx.x * blockDim.x + threadIdx.x;
    if (i < E1) atomicAdd(d1 + e1[E1 + i], 1.0f);
    if (i < E2) atomicAdd(d2 + e2[E2 + i], 1.0f);
}

// ================= conversions (single kernel) =================
__device__ __forceinline__ void split_bf16(float v, unsigned short& h, unsigned short& l) {
    bf16 hb = __float2bfloat16_rn(v);
    bf16 lb = __float2bfloat16_rn(v - __bfloat162float(hb));
    h = __bfloat16_as_ushort(hb);
    l = __bfloat16_as_ushort(lb);
}

#define NW_ITEMS 180224   // 131072 (W10) + 32768 (W20) + 16384 (W21)

__global__ void convert_all(const float* __restrict__ W10, const float* __restrict__ W20,
                            const float* __restrict__ W21, const float4* __restrict__ x,
                            bf16* __restrict__ w10h, bf16* __restrict__ w10l,
                            bf16* __restrict__ w20h, bf16* __restrict__ w20l,
                            bf16* __restrict__ w21h, bf16* __restrict__ w21l,
                            uint2* __restrict__ xh, uint2* __restrict__ xl, int xtotal4) {
    int i = blockIdx.x * blockDim.x + threadIdx.x;
    if (i < NW_ITEMS) {
        float v; bf16 *ph, *pl; int oi;
        if (i < 131072)      { int k = i >> 8, nn = i & 255; v = W10[i]; ph = w10h; pl = w10l; oi = nn * 512 + k; }
        else if (i < 163840) { int j = i - 131072; int k = j >> 6, nn = j & 63;  v = W20[j]; ph = w20h; pl = w20l; oi = nn * 512 + k; }
        else                 { int j = i - 163840; int k = j >> 8, nn = j & 255; v = W21[j]; ph = w21h; pl = w21l; oi = nn * 64 + k; }
        unsigned short h, l;
        split_bf16(v, h, l);
        ph[oi] = __ushort_as_bfloat16(h);
        pl[oi] = __ushort_as_bfloat16(l);
    } else {
        int j = i - NW_ITEMS;
        if (j >= xtotal4) return;
        float4 v = x[j];
        unsigned short h0, l0, h1, l1, h2, l2, h3, l3;
        split_bf16(v.x, h0, l0); split_bf16(v.y, h1, l1);
        split_bf16(v.z, h2, l2); split_bf16(v.w, h3, l3);
        uint2 uh, ul;
        uh.x = (uint32_t)h0 | ((uint32_t)h1 << 16);
        uh.y = (uint32_t)h2 | ((uint32_t)h3 << 16);
        ul.x = (uint32_t)l0 | ((uint32_t)l1 << 16);
        ul.y = (uint32_t)l2 | ((uint32_t)l3 << 16);
        xh[j] = uh; xl[j] = ul;
    }
}

// ================= zero (all scatter targets in one launch) =================
__global__ void zero_all(float4* __restrict__ t1, float4* __restrict__ t2a,
                         float4* __restrict__ t3, int n) {
    int i = blockIdx.x * blockDim.x + threadIdx.x;
    int n64 = n * 64;
    float4 z = make_float4(0.f, 0.f, 0.f, 0.f);
    if (i < n64) { t1[i] = z; return; }
    i -= n64;
    int n16 = n * 16;
    if (i < n16) { t2a[i] = z; return; }
    i -= n16;
    if (i < n16) { t3[i] = z; }
}

// ================= bf16-split GEMM via mma.sync + cp.async double buffer =================
// MODE 0: C = acc * rsqrt(deg[row])    (aux = deg counts)
// MODE 1: C = relu(acc + bias[col])    (aux = bias)
template<int BN, int MODE>
__global__ void __launch_bounds__(256, 1)
gemm_mma(const bf16* __restrict__ Ahi, const bf16* __restrict__ Alo,
         const bf16* __restrict__ Bhi, const bf16* __restrict__ Blo,
         float* __restrict__ C, const float* __restrict__ aux,
         int M, int N, int K)
{
    constexpr int LD = 72;
    constexpr int WN = BN / 4;
    constexpr int NFR = WN / 8;
    constexpr int AELEMS = 128 * LD;
    constexpr int BELEMS = BN * LD;
    constexpr int STAGE = 2 * AELEMS + 2 * BELEMS;
    constexpr int ABYTES = AELEMS * 2;
    constexpr int BBYTES = BELEMS * 2;
    constexpr int STAGEB = STAGE * 2;

    extern __shared__ bf16 smem[];

    const int tid  = threadIdx.x;
    const int wid  = tid >> 5;
    const int lane = tid & 31;
    const int wr = wid >> 2;
    const int wc = wid & 3;
    const int block_row = blockIdx.y * 128;
    const int block_col = blockIdx.x * BN;

    const uint32_t sb = smem_u32(smem);
    const int a_r0 = tid >> 3;
    const int a_c8 = (tid & 7) * 8;

    auto load_stage = [&](int ch, int s) {
        const int k0 = ch << 6;
        uint32_t st = sb + (uint32_t)(s * STAGEB);
        #pragma unroll
        for (int t = 0; t < 4; t++) {
            int r = a_r0 + t * 32;
            int gr = block_row + r;
            int sz = (gr < M) ? 16 : 0;
            uint32_t d = st + (uint32_t)((r * LD + a_c8) * 2);
            cp_async16(d, Ahi + (size_t)gr * K + k0 + a_c8, sz);
            cp_async16(d + ABYTES, Alo + (size_t)gr * K + k0 + a_c8, sz);
        }
        #pragma unroll
        for (int t = 0; t < BN / 32; t++) {
            int r = a_r0 + t * 32;
            uint32_t d = st + (uint32_t)(2 * ABYTES + (r * LD + a_c8) * 2);
            cp_async16(d, Bhi + (size_t)(block_col + r) * K + k0 + a_c8, 16);
            cp_async16(d + BBYTES, Blo + (size_t)(block_col + r) * K + k0 + a_c8, 16);
        }
        CP_COMMIT();
    };

    const int a_r = lane & 15;
    const int a_k = (lane >> 4) << 3;
    const int b_r = lane & 7;
    const int b_k = ((lane >> 3) & 1) << 3;

    float acc[4][NFR][4];
    #pragma unroll
    for (int mi = 0; mi < 4; mi++)
        #pragma unroll
        for (int ni = 0; ni < NFR; ni++)
            #pragma unroll
            for (int q = 0; q < 4; q++) acc[mi][ni][q] = 0.f;

    const int nch = K >> 6;
    load_stage(0, 0);

    for (int ch = 0; ch < nch; ch++) {
        if (ch + 1 < nch) { load_stage(ch + 1, (ch + 1) & 1); CP_WAIT(1); }
        else              { CP_WAIT(0); }
        __syncthreads();

        uint32_t st = sb + (uint32_t)((ch & 1) * STAGEB);
        #pragma unroll
        for (int ks = 0; ks < 4; ks++) {
            uint32_t ah[4][4], al[4][4];
            #pragma unroll
            for (int mi = 0; mi < 4; mi++) {
                uint32_t ad = st + (uint32_t)(((wr * 64 + mi * 16 + a_r) * LD + ks * 16 + a_k) * 2);
                LDM_X4(ah[mi], ad);
                LDM_X4(al[mi], ad + ABYTES);
            }
            #pragma unroll
            for (int ni = 0; ni < NFR; ni++) {
                uint32_t bd = st + (uint32_t)(2 * ABYTES + ((wc * WN + ni * 8 + b_r) * LD + ks * 16 + b_k) * 2);
                uint32_t bh[2], bl[2];
                LDM_X2(bh, bd);
                LDM_X2(bl, bd + BBYTES);
                #pragma unroll
                for (int mi = 0; mi < 4; mi++) {
                    mma16816(acc[mi][ni], ah[mi], bh);
                    mma16816(acc[mi][ni], ah[mi], bl);
                    mma16816(acc[mi][ni], al[mi], bh);
                }
            }
        }
        __syncthreads();
    }

    // ---- epilogue ----
    const int tq = lane >> 2;
    const int tr = (lane & 3) * 2;
    #pragma unroll
    for (int mi = 0; mi < 4; mi++) {
        int r0 = block_row + wr * 64 + mi * 16 + tq;
        int r1 = r0 + 8;
        float s0 = 0.f, s1 = 0.f;
        if (MODE == 0) {
            s0 = (r0 < M) ? rsqrtf(aux[r0]) : 0.f;
            s1 = (r1 < M) ? rsqrtf(aux[r1]) : 0.f;
        }
        #pragma unroll
        for (int ni = 0; ni < NFR; ni++) {
            int cc = block_col + wc * WN + ni * 8 + tr;
            if (MODE == 0) {
                if (r0 < M) {
                    float2 v = make_float2(acc[mi][ni][0] * s0, acc[mi][ni][1] * s0);
                    *(float2*)(C + (size_t)r0 * N + cc) = v;
                }
                if (r1 < M) {
                    float2 v = make_float2(acc[mi][ni][2] * s1, acc[mi][ni][3] * s1);
                    *(float2*)(C + (size_t)r1 * N + cc) = v;
                }
            } else {
                float b0 = aux[cc], b1 = aux[cc + 1];
                if (r0 < M) {
                    float2 v = make_float2(fmaxf(acc[mi][ni][0] + b0, 0.f),
                                           fmaxf(acc[mi][ni][1] + b1, 0.f));
                    *(float2*)(C + (size_t)r0 * N + cc) = v;
                }
                if (r1 < M) {
                    float2 v = make_float2(fmaxf(acc[mi][ni][2] + b0, 0.f),
                                           fmaxf(acc[mi][ni][3] + b1, 0.f));
                    *(float2*)(C + (size_t)r1 * N + cc) = v;
                }
            }
        }
    }
}

// ================= edge scatter: T[dst] += H'[src] (rows pre-scaled) =================
__device__ __forceinline__ void red_add4(float* p, float4 v) {
    asm volatile("red.global.add.v4.f32 [%0], {%1,%2,%3,%4};"
                 :: "l"(p), "f"(v.x), "f"(v.y), "f"(v.z), "f"(v.w) : "memory");
}
__device__ __forceinline__ void red_add2(float* p, float x, float y) {
    asm volatile("red.global.add.v2.f32 [%0], {%1,%2};"
                 :: "l"(p), "f"(x), "f"(y) : "memory");
}

__global__ void scatter_d256(const float* __restrict__ H, float* __restrict__ T,
                             const int* __restrict__ ei, int E) {
    int w = (blockIdx.x * blockDim.x + threadIdx.x) >> 5;
    if (w >= E) return;
    int lane = threadIdx.x & 31;
    int src = ei[w];
    int dst = ei[E + w];
    const float4* hs = (const float4*)(H + (size_t)src * 256);
    float* tp = T + (size_t)dst * 256;
    red_add4(tp + lane * 4, hs[lane]);
    red_add4(tp + 128 + lane * 4, hs[lane + 32]);
}

__global__ void scatter_d64(const float* __restrict__ H, float* __restrict__ T,
                            const int* __restrict__ ei, int E) {
    int w = (blockIdx.x * blockDim.x + threadIdx.x) >> 5;
    if (w >= E) return;
    int lane = threadIdx.x & 31;
    int src = ei[w];
    int dst = ei[E + w];
    float2 v = ((const float2*)(H + (size_t)src * 64))[lane];
    red_add2(T + (size_t)dst * 64 + lane * 2, v.x, v.y);
}

// ================= epilogues =================
// layer1: T1 = relu((T1 + H)*dinv1 + b10)
__global__ void epi_d256(float* __restrict__ T, const float* __restrict__ H,
                         const float* __restrict__ deg, const float* __restrict__ b, int n) {
    int idx = blockIdx.x * blockDim.x + threadIdx.x;
    if (idx >= n * 64) return;
    int i = idx >> 6;
    int j4 = (idx & 63) << 2;
    float dv = rsqrtf(deg[i]);
    size_t off = (size_t)i * 256 + j4;
    float4 t = *(float4*)(T + off);
    float4 h = *(const float4*)(H + off);
    float4 bb = *(const float4*)(b + j4);
    float4 r;
    r.x = fmaxf(fmaf(t.x + h.x, dv, bb.x), 0.f);
    r.y = fmaxf(fmaf(t.y + h.y, dv, bb.y), 0.f);
    r.z = fmaxf(fmaf(t.z + h.z, dv, bb.z), 0.f);
    r.w = fmaxf(fmaf(t.w + h.w, dv, bb.w), 0.f);
    *(float4*)(T + off) = r;
}

// layer2 finish + pre-scale for next propagation:
// s = ((T2a + H2a)*dinv2 + b20) * dinv2, written IN PLACE over H2a
__global__ void epi_s(const float* __restrict__ T, float* __restrict__ H,
                      const float* __restrict__ deg, const float* __restrict__ b, int n) {
    int idx = blockIdx.x * blockDim.x + threadIdx.x;
    if (idx >= n * 16) return;
    int i = idx >> 4;
    int j4 = (idx & 15) << 2;
    float dv = rsqrtf(deg[i]);
    size_t off = (size_t)i * 64 + j4;
    float4 t = *(const float4*)(T + off);
    float4 h = *(float4*)(H + off);
    float4 bb = *(const float4*)(b + j4);
    float4 r;
    r.x = fmaf(t.x + h.x, dv, bb.x) * dv;
    r.y = fmaf(t.y + h.y, dv, bb.y) * dv;
    r.z = fmaf(t.z + h.z, dv, bb.z) * dv;
    r.w = fmaf(t.w + h.w, dv, bb.w) * dv;
    *(float4*)(H + off) = r;
}

// layer3 gather-finish: G = (T3 + s)*dinv2, emitted as bf16 hi/lo for GEMM3
__global__ void epi_emitG(const float* __restrict__ T, const float* __restrict__ S,
                          const float* __restrict__ deg,
                          uint2* __restrict__ gh, uint2* __restrict__ gl, int n) {
    int idx = blockIdx.x * blockDim.x + threadIdx.x;
    if (idx >= n * 16) return;
    int i = idx >> 4;
    float dv = rsqrtf(deg[i]);
    size_t off = (size_t)i * 64 + ((idx & 15) << 2);
    float4 t = *(const float4*)(T + off);
    float4 s = *(const float4*)(S + off);
    float4 r;
    r.x = (t.x + s.x) * dv;
    r.y = (t.y + s.y) * dv;
    r.z = (t.z + s.z) * dv;
    r.w = (t.w + s.w) * dv;
    unsigned short h0, l0, h1, l1, h2, l2, h3, l3;
    split_bf16(r.x, h0, l0); split_bf16(r.y, h1, l1);
    split_bf16(r.z, h2, l2); split_bf16(r.w, h3, l3);
    uint2 uh, ul;
    uh.x = (uint32_t)h0 | ((uint32_t)h1 << 16);
    uh.y = (uint32_t)h2 | ((uint32_t)h3 << 16);
    ul.x = (uint32_t)l0 | ((uint32_t)l1 << 16);
    ul.y = (uint32_t)l2 | ((uint32_t)l3 << 16);
    gh[idx] = uh; gl[idx] = ul;
}

// ================= final: out = (A1 + A2) @ Wfc + bfc =================
__global__ void final_fc(const float* __restrict__ A1, const float* __restrict__ A2,
                         const float* __restrict__ W, const float* __restrict__ b,
                         float* __restrict__ out, int n) {
    __shared__ float Ws[D1][17];
    __shared__ float bs[CLS];
    for (int i = threadIdx.x; i < D1 * CLS; i += blockDim.x)
        Ws[i >> 4][i & 15] = W[i];
    if (threadIdx.x < CLS) bs[threadIdx.x] = b[threadIdx.x];
    __syncthreads();

    int warp = threadIdx.x >> 5;
    int lane = threadIdx.x & 31;
    int row = blockIdx.x * (blockDim.x >> 5) + warp;
    if (row >= n) return;

    float acc[CLS];
    #pragma unroll
    for (int c = 0; c < CLS; c++) acc[c] = 0.f;

    const float* r1 = A1 + (size_t)row * D1;
    const float* r2 = A2 + (size_t)row * D1;
    #pragma unroll
    for (int t = 0; t < D1 / 32; t++) {
        int j = lane + t * 32;
        float s = r1[j] + r2[j];
        #pragma unroll
        for (int c = 0; c < CLS; c++)
            acc[c] = fmaf(s, Ws[j][c], acc[c]);
    }
    #pragma unroll
    for (int off = 16; off; off >>= 1)
        #pragma unroll
        for (int c = 0; c < CLS; c++)
            acc[c] += __shfl_down_sync(0xffffffffu, acc[c], off);

    if (lane == 0) {
        float* o = out + (size_t)row * CLS;
        #pragma unroll
        for (int c = 0; c < CLS; c++) o[c] = acc[c] + bs[c];
    }
}

// ================= launch =================
extern "C" void kernel_launch(void* const* d_in, const int* in_sizes, int n_in,
                              void* d_out, int out_size)
{
    const float* x   = (const float*)d_in[0];
    const int*   e1  = (const int*)d_in[1];
    const int*   e2  = (const int*)d_in[2];
    const float* W10 = (const float*)d_in[3];
    const float* b10 = (const float*)d_in[4];
    const float* W20 = (const float*)d_in[5];
    const float* b20 = (const float*)d_in[6];
    const float* W21 = (const float*)d_in[7];
    const float* b21 = (const float*)d_in[8];
    const float* Wfc = (const float*)d_in[9];
    const float* bfc = (const float*)d_in[10];
    float* out = (float*)d_out;

    int n  = in_sizes[0] / F_IN;
    int E1 = in_sizes[1] / 2;
    int E2 = in_sizes[2] / 2;

    float *H, *T1, *T2b, *H2a, *T2a, *T3, *dg1, *dg2;
    bf16 *xh, *xl, *w10h, *w10l, *w20h, *w20l, *w21h, *w21l, *gh, *gl;
    cudaGetSymbolAddress((void**)&H,    g_H);
    cudaGetSymbolAddress((void**)&T1,   g_T1);
    cudaGetSymbolAddress((void**)&T2b,  g_T2b);
    cudaGetSymbolAddress((void**)&H2a,  g_H2a);
    cudaGetSymbolAddress((void**)&T2a,  g_T2a);
    cudaGetSymbolAddress((void**)&T3,   g_T3);
    cudaGetSymbolAddress((void**)&dg1,  g_deg1);
    cudaGetSymbolAddress((void**)&dg2,  g_deg2);
    cudaGetSymbolAddress((void**)&xh,   g_xhi);
    cudaGetSymbolAddress((void**)&xl,   g_xlo);
    cudaGetSymbolAddress((void**)&w10h, g_w10h);
    cudaGetSymbolAddress((void**)&w10l, g_w10l);
    cudaGetSymbolAddress((void**)&w20h, g_w20h);
    cudaGetSymbolAddress((void**)&w20l, g_w20l);
    cudaGetSymbolAddress((void**)&w21h, g_w21h);
    cudaGetSymbolAddress((void**)&w21l, g_w21l);
    cudaGetSymbolAddress((void**)&gh,   g_gh);
    cudaGetSymbolAddress((void**)&gl,   g_gl);

    const int SMEM128 = 2 * (2 * 128 * 72 + 2 * 128 * 72) * 2;  // 147456
    const int SMEM64  = 2 * (2 * 128 * 72 + 2 * 64 * 72) * 2;   // 110592
    cudaFuncSetAttribute((gemm_mma<128, 0>), cudaFuncAttributeMaxDynamicSharedMemorySize, SMEM128);
    cudaFuncSetAttribute((gemm_mma<64, 0>),  cudaFuncAttributeMaxDynamicSharedMemorySize, SMEM64);
    cudaFuncSetAttribute((gemm_mma<128, 1>), cudaFuncAttributeMaxDynamicSharedMemorySize, SMEM128);

    const int tb = 256;
    int Emax = E1 > E2 ? E1 : E2;
    int mtiles = (n + 127) / 128;
    dim3 grid1(D1 / 128, mtiles);
    dim3 grid2(1, mtiles);
    int scat1Blocks = (int)(((size_t)E1 * 32 + tb - 1) / tb);
    int scat2Blocks = (int)(((size_t)E2 * 32 + tb - 1) / tb);
    int cvtItems = NW_ITEMS + n * 128;

    // 0-1: degree counts (self loop included via init=1)
    deg_init<<<(n + tb - 1) / tb, tb>>>(dg1, dg2, n);
    deg_count<<<(Emax + tb - 1) / tb, tb>>>(e1, e2, dg1, dg2, E1, E2);

    // 2: all bf16 conversions
    convert_all<<<(cvtItems + tb - 1) / tb, tb>>>(W10, W20, W21, (const float4*)x,
                                                  w10h, w10l, w20h, w20l, w21h, w21l,
                                                  (uint2*)xh, (uint2*)xl, n * 128);

    // 3: GEMM1 (profiled slot): H = (x@W10)*dinv1
    gemm_mma<128, 0><<<grid1, tb, SMEM128>>>(xh, xl, w10h, w10l, H, dg1, n, D1, F_IN);

    // 4: zero all scatter targets
    zero_all<<<(n * 96 + tb - 1) / tb, tb>>>((float4*)T1, (float4*)T2a, (float4*)T3, n);

    // 5-6: layer 1 propagate + epilogue (relu)  -> T1 = h1
    scatter_d256<<<scat1Blocks, tb>>>(H, T1, e1, E1);
    epi_d256<<<(n * 64 + tb - 1) / tb, tb>>>(T1, H, dg1, b10, n);

    // 7-9: layer 2: H2a = (x@W20)*dinv2 ; propagate ; s = (h2a)*dinv2 in place
    gemm_mma<64, 0><<<grid2, tb, SMEM64>>>(xh, xl, w20h, w20l, H2a, dg2, n, D2, F_IN);
    scatter_d64<<<scat2Blocks, tb>>>(H2a, T2a, e2, E2);
    epi_s<<<(n * 16 + tb - 1) / tb, tb>>>(T2a, H2a, dg2, b20, n);

    // 10-11: layer 3 propagation at 64 dims: T3 += s[src] ; G = (T3+s)*dinv2 -> bf16
    scatter_d64<<<scat2Blocks, tb>>>(H2a, T3, e2, E2);
    epi_emitG<<<(n * 16 + tb - 1) / tb, tb>>>(T3, H2a, dg2, (uint2*)gh, (uint2*)gl, n);

    // 12: GEMM3 with fused bias+relu: T2b = relu(G@W21 + b21) = h2
    gemm_mma<128, 1><<<grid1, tb, SMEM128>>>(gh, gl, w21h, w21l, T2b, b21, n, D1, D2);

    // 13: final dense
    final_fc<<<(n + 7) / 8, tb>>>(T1, T2b, Wfc, bfc, out, n);
}

// round 15
// speedup vs baseline: 2.2564x; 1.0320x over previous
#include <cuda_runtime.h>
#include <cuda_bf16.h>
#include <cstdint>

typedef __nv_bfloat16 bf16;

#define F_IN 512
#define D1   256
#define D2   64
#define CLS  16
#define MAXN 50176

// ---------------- scratch (device globals; no allocation allowed) ----------------
__device__ float g_H[MAXN * D1];     // GEMM1/(x@W10)*dinv1 output
__device__ float g_T1[MAXN * D1];    // layer1 scatter target -> h1
__device__ float g_T2b[MAXN * D1];   // h2 (GEMM3 output, bias+relu)
__device__ float g_H2a[MAXN * D2];   // (x@W20)*dinv2, later s = h2a*dinv2 (in place)
__device__ float g_T2a[MAXN * D2];   // layer2 scatter target
__device__ float g_T3[MAXN * D2];    // layer3 (64-dim) scatter target
__device__ float g_deg1[MAXN];       // degree counts (incl self loop)
__device__ float g_deg2[MAXN];
__device__ bf16  g_xhi[MAXN * F_IN];
__device__ bf16  g_xlo[MAXN * F_IN];
__device__ bf16  g_w10h[D1 * F_IN];
__device__ bf16  g_w10l[D1 * F_IN];
__device__ bf16  g_w20h[D2 * F_IN];
__device__ bf16  g_w20l[D2 * F_IN];
__device__ bf16  g_w21h[D1 * D2];
__device__ bf16  g_w21l[D1 * D2];
__device__ bf16  g_gh[MAXN * D2];    // G = P2(h2a) bf16 hi
__device__ bf16  g_gl[MAXN * D2];    // G bf16 lo

// ================= helpers =================
__device__ __forceinline__ uint32_t smem_u32(const void* p) {
    uint32_t a;
    asm("{ .reg .u64 t; cvta.to.shared.u64 t, %1; cvt.u32.u64 %0, t; }" : "=r"(a) : "l"(p));
    return a;
}

#define LDM_X4(r, a)                                                              \
    asm volatile("ldmatrix.sync.aligned.m8n8.x4.shared.b16 {%0,%1,%2,%3}, [%4];"  \
        : "=r"((r)[0]), "=r"((r)[1]), "=r"((r)[2]), "=r"((r)[3]) : "r"(a))
#define LDM_X2(r, a)                                                              \
    asm volatile("ldmatrix.sync.aligned.m8n8.x2.shared.b16 {%0,%1}, [%2];"        \
        : "=r"((r)[0]), "=r"((r)[1]) : "r"(a))

__device__ __forceinline__ void mma16816(float* c, const uint32_t* a, const uint32_t* b) {
    asm volatile(
        "mma.sync.aligned.m16n8k16.row.col.f32.bf16.bf16.f32 "
        "{%0,%1,%2,%3}, {%4,%5,%6,%7}, {%8,%9}, {%0,%1,%2,%3};"
        : "+f"(c[0]), "+f"(c[1]), "+f"(c[2]), "+f"(c[3])
        : "r"(a[0]), "r"(a[1]), "r"(a[2]), "r"(a[3]), "r"(b[0]), "r"(b[1]));
}

__device__ __forceinline__ void cp_async16(uint32_t dst, const void* src, int sz) {
    asm volatile("cp.async.cg.shared.global [%0], [%1], 16, %2;"
                 :: "r"(dst), "l"(src), "r"(sz));
}
#define CP_COMMIT() asm volatile("cp.async.commit_group;")
#define CP_WAIT(n)  asm volatile("cp.async.wait_group %0;" :: "n"(n))

// ================= degree kernels =================
__global__ void deg_init(float* __restrict__ d1, float* __restrict__ d2, int n) {
    int i = blockIdx.x * blockDim.x + threadIdx.x;
    if (i < n) { d1[i] = 1.0f; d2[i] = 1.0f; }
}
__global__ void deg_count(const int* __restrict__ e1, const int* __restrict__ e2,
                          float* __restrict__ d1, float* __restrict__ d2, int E1, int E2) {
    int i = blockIdx.x * blockDim.x + threadIdx.x;
    if (i < E1) atomicAdd(d1 + e1[E1 + i], 1.0f);
    if (i < E2) atomicAdd(d2 + e2[E2 + i], 1.0f);
}

// ================= conversions (single kernel) =================
__device__ __forceinline__ void split_bf16(float v, unsigned short& h, unsigned short& l) {
    bf16 hb = __float2bfloat16_rn(v);
    bf16 lb = __float2bfloat16_rn(v - __bfloat162float(hb));
    h = __bfloat16_as_ushort(hb);
    l = __bfloat16_as_ushort(lb);
}

#define NW_ITEMS 180224   // 131072 (W10) + 32768 (W20) + 16384 (W21)

__global__ void convert_all(const float* __restrict__ W10, const float* __restrict__ W20,
                            const float* __restrict__ W21, const float4* __restrict__ x,
                            bf16* __restrict__ w10h, bf16* __restrict__ w10l,
                            bf16* __restrict__ w20h, bf16* __restrict__ w20l,
                            bf16* __restrict__ w21h, bf16* __restrict__ w21l,
                            uint2* __restrict__ xh, uint2* __restrict__ xl, int xtotal4) {
    int i = blockIdx.x * blockDim.x + threadIdx.x;
    if (i < NW_ITEMS) {
        float v; bf16 *ph, *pl; int oi;
        if (i < 131072)      { int k = i >> 8, nn = i & 255; v = W10[i]; ph = w10h; pl = w10l; oi = nn * 512 + k; }
        else if (i < 163840) { int j = i - 131072; int k = j >> 6, nn = j & 63;  v = W20[j]; ph = w20h; pl = w20l; oi = nn * 512 + k; }
        else                 { int j = i - 163840; int k = j >> 8, nn = j & 255; v = W21[j]; ph = w21h; pl = w21l; oi = nn * 64 + k; }
        unsigned short h, l;
        split_bf16(v, h, l);
        ph[oi] = __ushort_as_bfloat16(h);
        pl[oi] = __ushort_as_bfloat16(l);
    } else {
        int j = i - NW_ITEMS;
        if (j >= xtotal4) return;
        float4 v = x[j];
        unsigned short h0, l0, h1, l1, h2, l2, h3, l3;
        split_bf16(v.x, h0, l0); split_bf16(v.y, h1, l1);
        split_bf16(v.z, h2, l2); split_bf16(v.w, h3, l3);
        uint2 uh, ul;
        uh.x = (uint32_t)h0 | ((uint32_t)h1 << 16);
        uh.y = (uint32_t)h2 | ((uint32_t)h3 << 16);
        ul.x = (uint32_t)l0 | ((uint32_t)l1 << 16);
        ul.y = (uint32_t)l2 | ((uint32_t)l3 << 16);
        xh[j] = uh; xl[j] = ul;
    }
}

// ================= zero (all scatter targets in one launch) =================
__global__ void zero_all(float4* __restrict__ t1, float4* __restrict__ t2a,
                         float4* __restrict__ t3, int n) {
    int i = blockIdx.x * blockDim.x + threadIdx.x;
    int n64 = n * 64;
    float4 z = make_float4(0.f, 0.f, 0.f, 0.f);
    if (i < n64) { t1[i] = z; return; }
    i -= n64;
    int n16 = n * 16;
    if (i < n16) { t2a[i] = z; return; }
    i -= n16;
    if (i < n16) { t3[i] = z; }
}

// ================= bf16-split GEMM: BM=64, 2 CTAs/SM =================
// MODE 0: C = acc * rsqrt(deg[row])    (aux = deg counts)
// MODE 1: C = relu(acc + bias[col])    (aux = bias)
// BM=64, BN template, BK=64, 256 threads = 8 warps (2x4), warp tile 32 x (BN/4).
template<int BN, int MODE>
__global__ void __launch_bounds__(256, 2)
gemm_mma(const bf16* __restrict__ Ahi, const bf16* __restrict__ Alo,
         const bf16* __restrict__ Bhi, const bf16* __restrict__ Blo,
         float* __restrict__ C, const float* __restrict__ aux,
         int M, int N, int K)
{
    constexpr int LD = 72;
    constexpr int WN = BN / 4;
    constexpr int NFR = WN / 8;
    constexpr int AELEMS = 64 * LD;            // one A term
    constexpr int BELEMS = BN * LD;
    constexpr int STAGE = 2 * AELEMS + 2 * BELEMS;
    constexpr int ABYTES = AELEMS * 2;
    constexpr int BBYTES = BELEMS * 2;
    constexpr int STAGEB = STAGE * 2;

    extern __shared__ bf16 smem[];

    const int tid  = threadIdx.x;
    const int wid  = tid >> 5;
    const int lane = tid & 31;
    const int wr = wid >> 2;                   // 0..1, 32 rows each
    const int wc = wid & 3;                    // 0..3, WN cols each
    const int block_row = blockIdx.y * 64;
    const int block_col = blockIdx.x * BN;

    const uint32_t sb = smem_u32(smem);
    const int a_r0 = tid >> 3;                 // 0..31
    const int a_c8 = (tid & 7) * 8;

    auto load_stage = [&](int ch, int s) {
        const int k0 = ch << 6;
        uint32_t st = sb + (uint32_t)(s * STAGEB);
        #pragma unroll
        for (int t = 0; t < 2; t++) {          // 64 A rows
            int r = a_r0 + t * 32;
            int gr = block_row + r;
            int sz = (gr < M) ? 16 : 0;
            uint32_t d = st + (uint32_t)((r * LD + a_c8) * 2);
            cp_async16(d, Ahi + (size_t)gr * K + k0 + a_c8, sz);
            cp_async16(d + ABYTES, Alo + (size_t)gr * K + k0 + a_c8, sz);
        }
        #pragma unroll
        for (int t = 0; t < BN / 32; t++) {    // BN B rows
            int r = a_r0 + t * 32;
            uint32_t d = st + (uint32_t)(2 * ABYTES + (r * LD + a_c8) * 2);
            cp_async16(d, Bhi + (size_t)(block_col + r) * K + k0 + a_c8, 16);
            cp_async16(d + BBYTES, Blo + (size_t)(block_col + r) * K + k0 + a_c8, 16);
        }
        CP_COMMIT();
    };

    const int a_r = lane & 15;
    const int a_k = (lane >> 4) << 3;
    const int b_r = lane & 7;
    const int b_k = ((lane >> 3) & 1) << 3;

    float acc[2][NFR][4];
    #pragma unroll
    for (int mi = 0; mi < 2; mi++)
        #pragma unroll
        for (int ni = 0; ni < NFR; ni++)
            #pragma unroll
            for (int q = 0; q < 4; q++) acc[mi][ni][q] = 0.f;

    const int nch = K >> 6;
    load_stage(0, 0);

    for (int ch = 0; ch < nch; ch++) {
        if (ch + 1 < nch) { load_stage(ch + 1, (ch + 1) & 1); CP_WAIT(1); }
        else              { CP_WAIT(0); }
        __syncthreads();

        uint32_t st = sb + (uint32_t)((ch & 1) * STAGEB);
        #pragma unroll
        for (int ks = 0; ks < 4; ks++) {
            uint32_t ah[2][4], al[2][4];
            #pragma unroll
            for (int mi = 0; mi < 2; mi++) {
                uint32_t ad = st + (uint32_t)(((wr * 32 + mi * 16 + a_r) * LD + ks * 16 + a_k) * 2);
                LDM_X4(ah[mi], ad);
                LDM_X4(al[mi], ad + ABYTES);
            }
            #pragma unroll
            for (int ni = 0; ni < NFR; ni++) {
                uint32_t bd = st + (uint32_t)(2 * ABYTES + ((wc * WN + ni * 8 + b_r) * LD + ks * 16 + b_k) * 2);
                uint32_t bh[2], bl[2];
                LDM_X2(bh, bd);
                LDM_X2(bl, bd + BBYTES);
                #pragma unroll
                for (int mi = 0; mi < 2; mi++) {
                    mma16816(acc[mi][ni], ah[mi], bh);
                    mma16816(acc[mi][ni], ah[mi], bl);
                    mma16816(acc[mi][ni], al[mi], bh);
                }
            }
        }
        __syncthreads();
    }

    // ---- epilogue ----
    const int tq = lane >> 2;
    const int tr = (lane & 3) * 2;
    #pragma unroll
    for (int mi = 0; mi < 2; mi++) {
        int r0 = block_row + wr * 32 + mi * 16 + tq;
        int r1 = r0 + 8;
        float s0 = 0.f, s1 = 0.f;
        if (MODE == 0) {
            s0 = (r0 < M) ? rsqrtf(aux[r0]) : 0.f;
            s1 = (r1 < M) ? rsqrtf(aux[r1]) : 0.f;
        }
        #pragma unroll
        for (int ni = 0; ni < NFR; ni++) {
            int cc = block_col + wc * WN + ni * 8 + tr;
            if (MODE == 0) {
                if (r0 < M) {
                    float2 v = make_float2(acc[mi][ni][0] * s0, acc[mi][ni][1] * s0);
                    *(float2*)(C + (size_t)r0 * N + cc) = v;
                }
                if (r1 < M) {
                    float2 v = make_float2(acc[mi][ni][2] * s1, acc[mi][ni][3] * s1);
                    *(float2*)(C + (size_t)r1 * N + cc) = v;
                }
            } else {
                float b0 = aux[cc], b1 = aux[cc + 1];
                if (r0 < M) {
                    float2 v = make_float2(fmaxf(acc[mi][ni][0] + b0, 0.f),
                                           fmaxf(acc[mi][ni][1] + b1, 0.f));
                    *(float2*)(C + (size_t)r0 * N + cc) = v;
                }
                if (r1 < M) {
                    float2 v = make_float2(fmaxf(acc[mi][ni][2] + b0, 0.f),
                                           fmaxf(acc[mi][ni][3] + b1, 0.f));
                    *(float2*)(C + (size_t)r1 * N + cc) = v;
                }
            }
        }
    }
}

// ================= edge scatter: T[dst] += H'[src] (rows pre-scaled) =================
__device__ __forceinline__ void red_add4(float* p, float4 v) {
    asm volatile("red.global.add.v4.f32 [%0], {%1,%2,%3,%4};"
                 :: "l"(p), "f"(v.x), "f"(v.y), "f"(v.z), "f"(v.w) : "memory");
}
__device__ __forceinline__ void red_add2(float* p, float x, float y) {
    asm volatile("red.global.add.v2.f32 [%0], {%1,%2};"
                 :: "l"(p), "f"(x), "f"(y) : "memory");
}

__global__ void scatter_d256(const float* __restrict__ H, float* __restrict__ T,
                             const int* __restrict__ ei, int E) {
    int w = (blockIdx.x * blockDim.x + threadIdx.x) >> 5;
    if (w >= E) return;
    int lane = threadIdx.x & 31;
    int src = ei[w];
    int dst = ei[E + w];
    const float4* hs = (const float4*)(H + (size_t)src * 256);
    float* tp = T + (size_t)dst * 256;
    red_add4(tp + lane * 4, hs[lane]);
    red_add4(tp + 128 + lane * 4, hs[lane + 32]);
}

__global__ void scatter_d64(const float* __restrict__ H, float* __restrict__ T,
                            const int* __restrict__ ei, int E) {
    int w = (blockIdx.x * blockDim.x + threadIdx.x) >> 5;
    if (w >= E) return;
    int lane = threadIdx.x & 31;
    int src = ei[w];
    int dst = ei[E + w];
    float2 v = ((const float2*)(H + (size_t)src * 64))[lane];
    red_add2(T + (size_t)dst * 64 + lane * 2, v.x, v.y);
}

// ================= epilogues =================
// layer1: T1 = relu((T1 + H)*dinv1 + b10)
__global__ void epi_d256(float* __restrict__ T, const float* __restrict__ H,
                         const float* __restrict__ deg, const float* __restrict__ b, int n) {
    int idx = blockIdx.x * blockDim.x + threadIdx.x;
    if (idx >= n * 64) return;
    int i = idx >> 6;
    int j4 = (idx & 63) << 2;
    float dv = rsqrtf(deg[i]);
    size_t off = (size_t)i * 256 + j4;
    float4 t = *(float4*)(T + off);
    float4 h = *(const float4*)(H + off);
    float4 bb = *(const float4*)(b + j4);
    float4 r;
    r.x = fmaxf(fmaf(t.x + h.x, dv, bb.x), 0.f);
    r.y = fmaxf(fmaf(t.y + h.y, dv, bb.y), 0.f);
    r.z = fmaxf(fmaf(t.z + h.z, dv, bb.z), 0.f);
    r.w = fmaxf(fmaf(t.w + h.w, dv, bb.w), 0.f);
    *(float4*)(T + off) = r;
}

// layer2 finish + pre-scale for next propagation:
// s = ((T2a + H2a)*dinv2 + b20) * dinv2, written IN PLACE over H2a
__global__ void epi_s(const float* __restrict__ T, float* __restrict__ H,
                      const float* __restrict__ deg, const float* __restrict__ b, int n) {
    int idx = blockIdx.x * blockDim.x + threadIdx.x;
    if (idx >= n * 16) return;
    int i = idx >> 4;
    int j4 = (idx & 15) << 2;
    float dv = rsqrtf(deg[i]);
    size_t off = (size_t)i * 64 + j4;
    float4 t = *(const float4*)(T + off);
    float4 h = *(float4*)(H + off);
    float4 bb = *(const float4*)(b + j4);
    float4 r;
    r.x = fmaf(t.x + h.x, dv, bb.x) * dv;
    r.y = fmaf(t.y + h.y, dv, bb.y) * dv;
    r.z = fmaf(t.z + h.z, dv, bb.z) * dv;
    r.w = fmaf(t.w + h.w, dv, bb.w) * dv;
    *(float4*)(H + off) = r;
}

// layer3 gather-finish: G = (T3 + s)*dinv2, emitted as bf16 hi/lo for GEMM3
__global__ void epi_emitG(const float* __restrict__ T, const float* __restrict__ S,
                          const float* __restrict__ deg,
                          uint2* __restrict__ gh, uint2* __restrict__ gl, int n) {
    int idx = blockIdx.x * blockDim.x + threadIdx.x;
    if (idx >= n * 16) return;
    int i = idx >> 4;
    float dv = rsqrtf(deg[i]);
    size_t off = (size_t)i * 64 + ((idx & 15) << 2);
    float4 t = *(const float4*)(T + off);
    float4 s = *(const float4*)(S + off);
    float4 r;
    r.x = (t.x + s.x) * dv;
    r.y = (t.y + s.y) * dv;
    r.z = (t.z + s.z) * dv;
    r.w = (t.w + s.w) * dv;
    unsigned short h0, l0, h1, l1, h2, l2, h3, l3;
    split_bf16(r.x, h0, l0); split_bf16(r.y, h1, l1);
    split_bf16(r.z, h2, l2); split_bf16(r.w, h3, l3);
    uint2 uh, ul;
    uh.x = (uint32_t)h0 | ((uint32_t)h1 << 16);
    uh.y = (uint32_t)h2 | ((uint32_t)h3 << 16);
    ul.x = (uint32_t)l0 | ((uint32_t)l1 << 16);
    ul.y = (uint32_t)l2 | ((uint32_t)l3 << 16);
    gh[idx] = uh; gl[idx] = ul;
}

// ================= final: out = (A1 + A2) @ Wfc + bfc =================
__global__ void final_fc(const float* __restrict__ A1, const float* __restrict__ A2,
                         const float* __restrict__ W, const float* __restrict__ b,
                         float* __restrict__ out, int n) {
    __shared__ float Ws[D1][17];
    __shared__ float bs[CLS];
    for (int i = threadIdx.x; i < D1 * CLS; i += blockDim.x)
        Ws[i >> 4][i & 15] = W[i];
    if (threadIdx.x < CLS) bs[threadIdx.x] = b[threadIdx.x];
    __syncthreads();

    int warp = threadIdx.x >> 5;
    int lane = threadIdx.x & 31;
    int row = blockIdx.x * (blockDim.x >> 5) + warp;
    if (row >= n) return;

    float acc[CLS];
    #pragma unroll
    for (int c = 0; c < CLS; c++) acc[c] = 0.f;

    const float* r1 = A1 + (size_t)row * D1;
    const float* r2 = A2 + (size_t)row * D1;
    #pragma unroll
    for (int t = 0; t < D1 / 32; t++) {
        int j = lane + t * 32;
        float s = r1[j] + r2[j];
        #pragma unroll
        for (int c = 0; c < CLS; c++)
            acc[c] = fmaf(s, Ws[j][c], acc[c]);
    }
    #pragma unroll
    for (int off = 16; off; off >>= 1)
        #pragma unroll
        for (int c = 0; c < CLS; c++)
            acc[c] += __shfl_down_sync(0xffffffffu, acc[c], off);

    if (lane == 0) {
        float* o = out + (size_t)row * CLS;
        #pragma unroll
        for (int c = 0; c < CLS; c++) o[c] = acc[c] + bs[c];
    }
}

// ================= launch =================
extern "C" void kernel_launch(void* const* d_in, const int* in_sizes, int n_in,
                              void* d_out, int out_size)
{
    const float* x   = (const float*)d_in[0];
    const int*   e1  = (const int*)d_in[1];
    const int*   e2  = (const int*)d_in[2];
    const float* W10 = (const float*)d_in[3];
    const float* b10 = (const float*)d_in[4];
    const float* W20 = (const float*)d_in[5];
    const float* b20 = (const float*)d_in[6];
    const float* W21 = (const float*)d_in[7];
    const float* b21 = (const float*)d_in[8];
    const float* Wfc = (const float*)d_in[9];
    const float* bfc = (const float*)d_in[10];
    float* out = (float*)d_out;

    int n  = in_sizes[0] / F_IN;
    int E1 = in_sizes[1] / 2;
    int E2 = in_sizes[2] / 2;

    float *H, *T1, *T2b, *H2a, *T2a, *T3, *dg1, *dg2;
    bf16 *xh, *xl, *w10h, *w10l, *w20h, *w20l, *w21h, *w21l, *gh, *gl;
    cudaGetSymbolAddress((void**)&H,    g_H);
    cudaGetSymbolAddress((void**)&T1,   g_T1);
    cudaGetSymbolAddress((void**)&T2b,  g_T2b);
    cudaGetSymbolAddress((void**)&H2a,  g_H2a);
    cudaGetSymbolAddress((void**)&T2a,  g_T2a);
    cudaGetSymbolAddress((void**)&T3,   g_T3);
    cudaGetSymbolAddress((void**)&dg1,  g_deg1);
    cudaGetSymbolAddress((void**)&dg2,  g_deg2);
    cudaGetSymbolAddress((void**)&xh,   g_xhi);
    cudaGetSymbolAddress((void**)&xl,   g_xlo);
    cudaGetSymbolAddress((void**)&w10h, g_w10h);
    cudaGetSymbolAddress((void**)&w10l, g_w10l);
    cudaGetSymbolAddress((void**)&w20h, g_w20h);
    cudaGetSymbolAddress((void**)&w20l, g_w20l);
    cudaGetSymbolAddress((void**)&w21h, g_w21h);
    cudaGetSymbolAddress((void**)&w21l, g_w21l);
    cudaGetSymbolAddress((void**)&gh,   g_gh);
    cudaGetSymbolAddress((void**)&gl,   g_gl);

    // per stage: (2*64*72 + 2*BN*72)*2 bytes; two stages
    const int SMEM128 = 2 * (2 * 64 * 72 + 2 * 128 * 72) * 2;  // 110592
    const int SMEM64  = 2 * (2 * 64 * 72 + 2 * 64 * 72) * 2;   // 73728
    cudaFuncSetAttribute((gemm_mma<128, 0>), cudaFuncAttributeMaxDynamicSharedMemorySize, SMEM128);
    cudaFuncSetAttribute((gemm_mma<64, 0>),  cudaFuncAttributeMaxDynamicSharedMemorySize, SMEM64);
    cudaFuncSetAttribute((gemm_mma<128, 1>), cudaFuncAttributeMaxDynamicSharedMemorySize, SMEM128);

    const int tb = 256;
    int Emax = E1 > E2 ? E1 : E2;
    int mtiles = (n + 63) / 64;
    dim3 grid1(D1 / 128, mtiles);
    dim3 grid2(1, mtiles);
    int scat1Blocks = (int)(((size_t)E1 * 32 + tb - 1) / tb);
    int scat2Blocks = (int)(((size_t)E2 * 32 + tb - 1) / tb);
    int cvtItems = NW_ITEMS + n * 128;

    // 0-1: degree counts (self loop included via init=1)
    deg_init<<<(n + tb - 1) / tb, tb>>>(dg1, dg2, n);
    deg_count<<<(Emax + tb - 1) / tb, tb>>>(e1, e2, dg1, dg2, E1, E2);

    // 2: all bf16 conversions
    convert_all<<<(cvtItems + tb - 1) / tb, tb>>>(W10, W20, W21, (const float4*)x,
                                                  w10h, w10l, w20h, w20l, w21h, w21l,
                                                  (uint2*)xh, (uint2*)xl, n * 128);

    // 3: GEMM1 (profiled slot): H = (x@W10)*dinv1
    gemm_mma<128, 0><<<grid1, tb, SMEM128>>>(xh, xl, w10h, w10l, H, dg1, n, D1, F_IN);

    // 4: zero all scatter targets
    zero_all<<<(n * 96 + tb - 1) / tb, tb>>>((float4*)T1, (float4*)T2a, (float4*)T3, n);

    // 5-6: layer 1 propagate + epilogue (relu)  -> T1 = h1
    scatter_d256<<<scat1Blocks, tb>>>(H, T1, e1, E1);
    epi_d256<<<(n * 64 + tb - 1) / tb, tb>>>(T1, H, dg1, b10, n);

    // 7-9: layer 2: H2a = (x@W20)*dinv2 ; propagate ; s = (h2a)*dinv2 in place
    gemm_mma<64, 0><<<grid2, tb, SMEM64>>>(xh, xl, w20h, w20l, H2a, dg2, n, D2, F_IN);
    scatter_d64<<<scat2Blocks, tb>>>(H2a, T2a, e2, E2);
    epi_s<<<(n * 16 + tb - 1) / tb, tb>>>(T2a, H2a, dg2, b20, n);

    // 10-11: layer 3 propagation at 64 dims: T3 += s[src] ; G = (T3+s)*dinv2 -> bf16
    scatter_d64<<<scat2Blocks, tb>>>(H2a, T3, e2, E2);
    epi_emitG<<<(n * 16 + tb - 1) / tb, tb>>>(T3, H2a, dg2, (uint2*)gh, (uint2*)gl, n);

    // 12: GEMM3 with fused bias+relu: T2b = relu(G@W21 + b21) = h2
    gemm_mma<128, 1><<<grid1, tb, SMEM128>>>(gh, gl, w21h, w21l, T2b, b21, n, D1, D2);

    // 13: final dense
    final_fc<<<(n + 7) / 8, tb>>>(T1, T2b, Wfc, bfc, out, n);
}

// round 17
// speedup vs baseline: 2.2710x; 1.0065x over previous
#include <cuda_runtime.h>
#include <cuda_bf16.h>
#include <cstdint>

typedef __nv_bfloat16 bf16;

#define F_IN 512
#define D1   256
#define D2   64
#define CLS  16
#define MAXN 50176

// ---------------- scratch (device globals; no allocation allowed) ----------------
__device__ float g_H[MAXN * D1];     // GEMM1/(x@W10)*dinv1 output
__device__ float g_T1[MAXN * D1];    // layer1 scatter target -> h1
__device__ float g_T2b[MAXN * D1];   // h2 (GEMM3 output, bias+relu)
__device__ float g_H2a[MAXN * D2];   // (x@W20)*dinv2, later s = h2a*dinv2 (in place)
__device__ float g_T2a[MAXN * D2];   // layer2 scatter target
__device__ float g_T3[MAXN * D2];    // layer3 (64-dim) scatter target
__device__ float g_deg1[MAXN];       // degree counts (incl self loop)
__device__ float g_deg2[MAXN];
__device__ bf16  g_xhi[MAXN * F_IN];
__device__ bf16  g_xlo[MAXN * F_IN];
__device__ bf16  g_w10h[D1 * F_IN];
__device__ bf16  g_w10l[D1 * F_IN];
__device__ bf16  g_w20h[D2 * F_IN];
__device__ bf16  g_w20l[D2 * F_IN];
__device__ bf16  g_w21h[D1 * D2];
__device__ bf16  g_w21l[D1 * D2];
__device__ bf16  g_gh[MAXN * D2];    // G = P2(h2a) bf16 hi
__device__ bf16  g_gl[MAXN * D2];    // G bf16 lo

// ================= helpers =================
__device__ __forceinline__ uint32_t smem_u32(const void* p) {
    uint32_t a;
    asm("{ .reg .u64 t; cvta.to.shared.u64 t, %1; cvt.u32.u64 %0, t; }" : "=r"(a) : "l"(p));
    return a;
}

#define LDM_X4(r, a)                                                              \
    asm volatile("ldmatrix.sync.aligned.m8n8.x4.shared.b16 {%0,%1,%2,%3}, [%4];"  \
        : "=r"((r)[0]), "=r"((r)[1]), "=r"((r)[2]), "=r"((r)[3]) : "r"(a))

__device__ __forceinline__ void mma16816(float* c, const uint32_t* a, const uint32_t* b) {
    asm volatile(
        "mma.sync.aligned.m16n8k16.row.col.f32.bf16.bf16.f32 "
        "{%0,%1,%2,%3}, {%4,%5,%6,%7}, {%8,%9}, {%0,%1,%2,%3};"
        : "+f"(c[0]), "+f"(c[1]), "+f"(c[2]), "+f"(c[3])
        : "r"(a[0]), "r"(a[1]), "r"(a[2]), "r"(a[3]), "r"(b[0]), "r"(b[1]));
}

__device__ __forceinline__ void cp_async16(uint32_t dst, const void* src, int sz) {
    asm volatile("cp.async.cg.shared.global [%0], [%1], 16, %2;"
                 :: "r"(dst), "l"(src), "r"(sz));
}
#define CP_COMMIT() asm volatile("cp.async.commit_group;")
#define CP_WAIT(n)  asm volatile("cp.async.wait_group %0;" :: "n"(n))

// ================= degree kernels =================
__global__ void deg_init(float* __restrict__ d1, float* __restrict__ d2, int n) {
    int i = blockIdx.x * blockDim.x + threadIdx.x;
    if (i < n) { d1[i] = 1.0f; d2[i] = 1.0f; }
}
__global__ void deg_count(const int* __restrict__ e1, const int* __restrict__ e2,
                          float* __restrict__ d1, float* __restrict__ d2, int E1, int E2) {
    int i = blockIdx.x * blockDim.x + threadIdx.x;
    if (i < E1) atomicAdd(d1 + e1[E1 + i], 1.0f);
    if (i < E2) atomicAdd(d2 + e2[E2 + i], 1.0f);
}

// ================= conversions (single kernel) =================
__device__ __forceinline__ void split_bf16(float v, unsigned short& h, unsigned short& l) {
    bf16 hb = __float2bfloat16_rn(v);
    bf16 lb = __float2bfloat16_rn(v - __bfloat162float(hb));
    h = __bfloat16_as_ushort(hb);
    l = __bfloat16_as_ushort(lb);
}

#define NW_ITEMS 180224   // 131072 (W10) + 32768 (W20) + 16384 (W21)

__global__ void convert_all(const float* __restrict__ W10, const float* __restrict__ W20,
                            const float* __restrict__ W21, const float4* __restrict__ x,
                            bf16* __restrict__ w10h, bf16* __restrict__ w10l,
                            bf16* __restrict__ w20h, bf16* __restrict__ w20l,
                            bf16* __restrict__ w21h, bf16* __restrict__ w21l,
                            uint2* __restrict__ xh, uint2* __restrict__ xl, int xtotal4) {
    int i = blockIdx.x * blockDim.x + threadIdx.x;
    if (i < NW_ITEMS) {
        float v; bf16 *ph, *pl; int oi;
        if (i < 131072)      { int k = i >> 8, nn = i & 255; v = W10[i]; ph = w10h; pl = w10l; oi = nn * 512 + k; }
        else if (i < 163840) { int j = i - 131072; int k = j >> 6, nn = j & 63;  v = W20[j]; ph = w20h; pl = w20l; oi = nn * 512 + k; }
        else                 { int j = i - 163840; int k = j >> 8, nn = j & 255; v = W21[j]; ph = w21h; pl = w21l; oi = nn * 64 + k; }
        unsigned short h, l;
        split_bf16(v, h, l);
        ph[oi] = __ushort_as_bfloat16(h);
        pl[oi] = __ushort_as_bfloat16(l);
    } else {
        int j = i - NW_ITEMS;
        if (j >= xtotal4) return;
        float4 v = x[j];
        unsigned short h0, l0, h1, l1, h2, l2, h3, l3;
        split_bf16(v.x, h0, l0); split_bf16(v.y, h1, l1);
        split_bf16(v.z, h2, l2); split_bf16(v.w, h3, l3);
        uint2 uh, ul;
        uh.x = (uint32_t)h0 | ((uint32_t)h1 << 16);
        uh.y = (uint32_t)h2 | ((uint32_t)h3 << 16);
        ul.x = (uint32_t)l0 | ((uint32_t)l1 << 16);
        ul.y = (uint32_t)l2 | ((uint32_t)l3 << 16);
        xh[j] = uh; xl[j] = ul;
    }
}

// ================= zero (all scatter targets in one launch) =================
__global__ void zero_all(float4* __restrict__ t1, float4* __restrict__ t2a,
                         float4* __restrict__ t3, int n) {
    int i = blockIdx.x * blockDim.x + threadIdx.x;
    int n64 = n * 64;
    float4 z = make_float4(0.f, 0.f, 0.f, 0.f);
    if (i < n64) { t1[i] = z; return; }
    i -= n64;
    int n16 = n * 16;
    if (i < n16) { t2a[i] = z; return; }
    i -= n16;
    if (i < n16) { t3[i] = z; }
}

// ================= bf16-split GEMM: BM=64, 2 CTAs/SM, single-sync pipeline =================
// MODE 0: C = acc * rsqrt(deg[row])    (aux = deg counts)
// MODE 1: C = relu(acc + bias[col])    (aux = bias)
// BM=64, BN template, BK=64, 256 threads = 8 warps (2x4), warp tile 32 x (BN/4).
template<int BN, int MODE>
__global__ void __launch_bounds__(256, 2)
gemm_mma(const bf16* __restrict__ Ahi, const bf16* __restrict__ Alo,
         const bf16* __restrict__ Bhi, const bf16* __restrict__ Blo,
         float* __restrict__ C, const float* __restrict__ aux,
         int M, int N, int K)
{
    constexpr int LD = 72;
    constexpr int WN = BN / 4;
    constexpr int NFR = WN / 8;                // n fragments per warp (4 or 2)
    constexpr int NP4 = NFR / 2;               // x4 B loads per term (2 or 1)
    constexpr int AELEMS = 64 * LD;
    constexpr int BELEMS = BN * LD;
    constexpr int STAGE = 2 * AELEMS + 2 * BELEMS;
    constexpr int ABYTES = AELEMS * 2;
    constexpr int BBYTES = BELEMS * 2;
    constexpr int STAGEB = STAGE * 2;

    extern __shared__ bf16 smem[];

    const int tid  = threadIdx.x;
    const int wid  = tid >> 5;
    const int lane = tid & 31;
    const int wr = wid >> 2;                   // 0..1, 32 rows each
    const int wc = wid & 3;                    // 0..3, WN cols each
    const int block_row = blockIdx.y * 64;
    const int block_col = blockIdx.x * BN;

    const uint32_t sb = smem_u32(smem);
    const int a_r0 = tid >> 3;                 // 0..31
    const int a_c8 = (tid & 7) * 8;

    auto load_stage = [&](int ch, int s) {
        const int k0 = ch << 6;
        uint32_t st = sb + (uint32_t)(s * STAGEB);
        #pragma unroll
        for (int t = 0; t < 2; t++) {          // 64 A rows
            int r = a_r0 + t * 32;
            int gr = block_row + r;
            int sz = (gr < M) ? 16 : 0;
            uint32_t d = st + (uint32_t)((r * LD + a_c8) * 2);
            cp_async16(d, Ahi + (size_t)gr * K + k0 + a_c8, sz);
            cp_async16(d + ABYTES, Alo + (size_t)gr * K + k0 + a_c8, sz);
        }
        #pragma unroll
        for (int t = 0; t < BN / 32; t++) {    // BN B rows
            int r = a_r0 + t * 32;
            uint32_t d = st + (uint32_t)(2 * ABYTES + (r * LD + a_c8) * 2);
            cp_async16(d, Bhi + (size_t)(block_col + r) * K + k0 + a_c8, 16);
            cp_async16(d + BBYTES, Blo + (size_t)(block_col + r) * K + k0 + a_c8, 16);
        }
        CP_COMMIT();
    };

    // ldmatrix lane mappings
    const int a_r = lane & 15;                 // A x4: m row
    const int a_k = (lane >> 4) << 3;          // A x4: k 0/8
    const int b_n = (lane & 7) + ((lane >> 4) << 3);  // B x4: n row within 16
    const int b_k = ((lane >> 3) & 1) << 3;           // B x4: k 0/8

    float acc[2][NFR][4];
    #pragma unroll
    for (int mi = 0; mi < 2; mi++)
        #pragma unroll
        for (int ni = 0; ni < NFR; ni++)
            #pragma unroll
            for (int q = 0; q < 4; q++) acc[mi][ni][q] = 0.f;

    const int nch = K >> 6;
    load_stage(0, 0);

    for (int ch = 0; ch < nch; ch++) {
        CP_WAIT(0);          // stage (ch&1) data arrived
        __syncthreads();     // also: everyone done reading stage ((ch+1)&1) from iter ch-1
        if (ch + 1 < nch) load_stage(ch + 1, (ch + 1) & 1);

        uint32_t st = sb + (uint32_t)((ch & 1) * STAGEB);
        #pragma unroll
        for (int ks = 0; ks < 4; ks++) {
            // A fragments (hi + lo) via x4
            uint32_t ah[2][4], al[2][4];
            #pragma unroll
            for (int mi = 0; mi < 2; mi++) {
                uint32_t ad = st + (uint32_t)(((wr * 32 + mi * 16 + a_r) * LD + ks * 16 + a_k) * 2);
                LDM_X4(ah[mi], ad);
                LDM_X4(al[mi], ad + ABYTES);
            }
            // B fragments (hi + lo) via x4: each load covers n=16, k=16 (2 fragments)
            uint32_t bh[NP4][4], bl[NP4][4];
            #pragma unroll
            for (int np = 0; np < NP4; np++) {
                uint32_t bd = st + (uint32_t)(2 * ABYTES +
                              ((wc * WN + np * 16 + b_n) * LD + ks * 16 + b_k) * 2);
                LDM_X4(bh[np], bd);
                LDM_X4(bl[np], bd + BBYTES);
            }
            #pragma unroll
            for (int ni = 0; ni < NFR; ni++) {
                const uint32_t* pbh = &bh[ni >> 1][(ni & 1) * 2];
                const uint32_t* pbl = &bl[ni >> 1][(ni & 1) * 2];
                #pragma unroll
                for (int mi = 0; mi < 2; mi++) {
                    mma16816(acc[mi][ni], ah[mi], pbh);
                    mma16816(acc[mi][ni], ah[mi], pbl);
                    mma16816(acc[mi][ni], al[mi], pbh);
                }
            }
        }
        // no trailing sync: next iteration's sync (after CP_WAIT) orders reuse
    }

    // ---- epilogue ----
    const int tq = lane >> 2;
    const int tr = (lane & 3) * 2;
    #pragma unroll
    for (int mi = 0; mi < 2; mi++) {
        int r0 = block_row + wr * 32 + mi * 16 + tq;
        int r1 = r0 + 8;
        float s0 = 0.f, s1 = 0.f;
        if (MODE == 0) {
            s0 = (r0 < M) ? rsqrtf(aux[r0]) : 0.f;
            s1 = (r1 < M) ? rsqrtf(aux[r1]) : 0.f;
        }
        #pragma unroll
        for (int ni = 0; ni < NFR; ni++) {
            int cc = block_col + wc * WN + ni * 8 + tr;
            if (MODE == 0) {
                if (r0 < M) {
                    float2 v = make_float2(acc[mi][ni][0] * s0, acc[mi][ni][1] * s0);
                    *(float2*)(C + (size_t)r0 * N + cc) = v;
                }
                if (r1 < M) {
                    float2 v = make_float2(acc[mi][ni][2] * s1, acc[mi][ni][3] * s1);
                    *(float2*)(C + (size_t)r1 * N + cc) = v;
                }
            } else {
                float b0 = aux[cc], b1 = aux[cc + 1];
                if (r0 < M) {
                    float2 v = make_float2(fmaxf(acc[mi][ni][0] + b0, 0.f),
                                           fmaxf(acc[mi][ni][1] + b1, 0.f));
                    *(float2*)(C + (size_t)r0 * N + cc) = v;
                }
                if (r1 < M) {
                    float2 v = make_float2(fmaxf(acc[mi][ni][2] + b0, 0.f),
                                           fmaxf(acc[mi][ni][3] + b1, 0.f));
                    *(float2*)(C + (size_t)r1 * N + cc) = v;
                }
            }
        }
    }
}

// ================= edge scatter: T[dst] += H'[src] (rows pre-scaled) =================
__device__ __forceinline__ void red_add4(float* p, float4 v) {
    asm volatile("red.global.add.v4.f32 [%0], {%1,%2,%3,%4};"
                 :: "l"(p), "f"(v.x), "f"(v.y), "f"(v.z), "f"(v.w) : "memory");
}
__device__ __forceinline__ void red_add2(float* p, float x, float y) {
    asm volatile("red.global.add.v2.f32 [%0], {%1,%2};"
                 :: "l"(p), "f"(x), "f"(y) : "memory");
}

__global__ void scatter_d256(const float* __restrict__ H, float* __restrict__ T,
                             const int* __restrict__ ei, int E) {
    int w = (blockIdx.x * blockDim.x + threadIdx.x) >> 5;
    if (w >= E) return;
    int lane = threadIdx.x & 31;
    int src = ei[w];
    int dst = ei[E + w];
    const float4* hs = (const float4*)(H + (size_t)src * 256);
    float* tp = T + (size_t)dst * 256;
    red_add4(tp + lane * 4, hs[lane]);
    red_add4(tp + 128 + lane * 4, hs[lane + 32]);
}

__global__ void scatter_d64(const float* __restrict__ H, float* __restrict__ T,
                            const int* __restrict__ ei, int E) {
    int w = (blockIdx.x * blockDim.x + threadIdx.x) >> 5;
    if (w >= E) return;
    int lane = threadIdx.x & 31;
    int src = ei[w];
    int dst = ei[E + w];
    float2 v = ((const float2*)(H + (size_t)src * 64))[lane];
    red_add2(T + (size_t)dst * 64 + lane * 2, v.x, v.y);
}

// ================= epilogues =================
// layer1: T1 = relu((T1 + H)*dinv1 + b10)
__global__ void epi_d256(float* __restrict__ T, const float* __restrict__ H,
                         const float* __restrict__ deg, const float* __restrict__ b, int n) {
    int idx = blockIdx.x * blockDim.x + threadIdx.x;
    if (idx >= n * 64) return;
    int i = idx >> 6;
    int j4 = (idx & 63) << 2;
    float dv = rsqrtf(deg[i]);
    size_t off = (size_t)i * 256 + j4;
    float4 t = *(float4*)(T + off);
    float4 h = *(const float4*)(H + off);
    float4 bb = *(const float4*)(b + j4);
    float4 r;
    r.x = fmaxf(fmaf(t.x + h.x, dv, bb.x), 0.f);
    r.y = fmaxf(fmaf(t.y + h.y, dv, bb.y), 0.f);
    r.z = fmaxf(fmaf(t.z + h.z, dv, bb.z), 0.f);
    r.w = fmaxf(fmaf(t.w + h.w, dv, bb.w), 0.f);
    *(float4*)(T + off) = r;
}

// layer2 finish + pre-scale for next propagation:
// s = ((T2a + H2a)*dinv2 + b20) * dinv2, written IN PLACE over H2a
__global__ void epi_s(const float* __restrict__ T, float* __restrict__ H,
                      const float* __restrict__ deg, const float* __restrict__ b, int n) {
    int idx = blockIdx.x * blockDim.x + threadIdx.x;
    if (idx >= n * 16) return;
    int i = idx >> 4;
    int j4 = (idx & 15) << 2;
    float dv = rsqrtf(deg[i]);
    size_t off = (size_t)i * 64 + j4;
    float4 t = *(const float4*)(T + off);
    float4 h = *(float4*)(H + off);
    float4 bb = *(const float4*)(b + j4);
    float4 r;
    r.x = fmaf(t.x + h.x, dv, bb.x) * dv;
    r.y = fmaf(t.y + h.y, dv, bb.y) * dv;
    r.z = fmaf(t.z + h.z, dv, bb.z) * dv;
    r.w = fmaf(t.w + h.w, dv, bb.w) * dv;
    *(float4*)(H + off) = r;
}

// layer3 gather-finish: G = (T3 + s)*dinv2, emitted as bf16 hi/lo for GEMM3
__global__ void epi_emitG(const float* __restrict__ T, const float* __restrict__ S,
                          const float* __restrict__ deg,
                          uint2* __restrict__ gh, uint2* __restrict__ gl, int n) {
    int idx = blockIdx.x * blockDim.x + threadIdx.x;
    if (idx >= n * 16) return;
    int i = idx >> 4;
    float dv = rsqrtf(deg[i]);
    size_t off = (size_t)i * 64 + ((idx & 15) << 2);
    float4 t = *(const float4*)(T + off);
    float4 s = *(const float4*)(S + off);
    float4 r;
    r.x = (t.x + s.x) * dv;
    r.y = (t.y + s.y) * dv;
    r.z = (t.z + s.z) * dv;
    r.w = (t.w + s.w) * dv;
    unsigned short h0, l0, h1, l1, h2, l2, h3, l3;
    split_bf16(r.x, h0, l0); split_bf16(r.y, h1, l1);
    split_bf16(r.z, h2, l2); split_bf16(r.w, h3, l3);
    uint2 uh, ul;
    uh.x = (uint32_t)h0 | ((uint32_t)h1 << 16);
    uh.y = (uint32_t)h2 | ((uint32_t)h3 << 16);
    ul.x = (uint32_t)l0 | ((uint32_t)l1 << 16);
    ul.y = (uint32_t)l2 | ((uint32_t)l3 << 16);
    gh[idx] = uh; gl[idx] = ul;
}

// ================= final: out = (A1 + A2) @ Wfc + bfc =================
__global__ void final_fc(const float* __restrict__ A1, const float* __restrict__ A2,
                         const float* __restrict__ W, const float* __restrict__ b,
                         float* __restrict__ out, int n) {
    __shared__ float Ws[D1][17];
    __shared__ float bs[CLS];
    for (int i = threadIdx.x; i < D1 * CLS; i += blockDim.x)
        Ws[i >> 4][i & 15] = W[i];
    if (threadIdx.x < CLS) bs[threadIdx.x] = b[threadIdx.x];
    __syncthreads();

    int warp = threadIdx.x >> 5;
    int lane = threadIdx.x & 31;
    int row = blockIdx.x * (blockDim.x >> 5) + warp;
    if (row >= n) return;

    float acc[CLS];
    #pragma unroll
    for (int c = 0; c < CLS; c++) acc[c] = 0.f;

    const float* r1 = A1 + (size_t)row * D1;
    const float* r2 = A2 + (size_t)row * D1;
    #pragma unroll
    for (int t = 0; t < D1 / 32; t++) {
        int j = lane + t * 32;
        float s = r1[j] + r2[j];
        #pragma unroll
        for (int c = 0; c < CLS; c++)
            acc[c] = fmaf(s, Ws[j][c], acc[c]);
    }
    #pragma unroll
    for (int off = 16; off; off >>= 1)
        #pragma unroll
        for (int c = 0; c < CLS; c++)
            acc[c] += __shfl_down_sync(0xffffffffu, acc[c], off);

    if (lane == 0) {
        float* o = out + (size_t)row * CLS;
        #pragma unroll
        for (int c = 0; c < CLS; c++) o[c] = acc[c] + bs[c];
    }
}

// ================= launch =================
extern "C" void kernel_launch(void* const* d_in, const int* in_sizes, int n_in,
                              void* d_out, int out_size)
{
    const float* x   = (const float*)d_in[0];
    const int*   e1  = (const int*)d_in[1];
    const int*   e2  = (const int*)d_in[2];
    const float* W10 = (const float*)d_in[3];
    const float* b10 = (const float*)d_in[4];
    const float* W20 = (const float*)d_in[5];
    const float* b20 = (const float*)d_in[6];
    const float* W21 = (const float*)d_in[7];
    const float* b21 = (const float*)d_in[8];
    const float* Wfc = (const float*)d_in[9];
    const float* bfc = (const float*)d_in[10];
    float* out = (float*)d_out;

    int n  = in_sizes[0] / F_IN;
    int E1 = in_sizes[1] / 2;
    int E2 = in_sizes[2] / 2;

    float *H, *T1, *T2b, *H2a, *T2a, *T3, *dg1, *dg2;
    bf16 *xh, *xl, *w10h, *w10l, *w20h, *w20l, *w21h, *w21l, *gh, *gl;
    cudaGetSymbolAddress((void**)&H,    g_H);
    cudaGetSymbolAddress((void**)&T1,   g_T1);
    cudaGetSymbolAddress((void**)&T2b,  g_T2b);
    cudaGetSymbolAddress((void**)&H2a,  g_H2a);
    cudaGetSymbolAddress((void**)&T2a,  g_T2a);
    cudaGetSymbolAddress((void**)&T3,   g_T3);
    cudaGetSymbolAddress((void**)&dg1,  g_deg1);
    cudaGetSymbolAddress((void**)&dg2,  g_deg2);
    cudaGetSymbolAddress((void**)&xh,   g_xhi);
    cudaGetSymbolAddress((void**)&xl,   g_xlo);
    cudaGetSymbolAddress((void**)&w10h, g_w10h);
    cudaGetSymbolAddress((void**)&w10l, g_w10l);
    cudaGetSymbolAddress((void**)&w20h, g_w20h);
    cudaGetSymbolAddress((void**)&w20l, g_w20l);
    cudaGetSymbolAddress((void**)&w21h, g_w21h);
    cudaGetSymbolAddress((void**)&w21l, g_w21l);
    cudaGetSymbolAddress((void**)&gh,   g_gh);
    cudaGetSymbolAddress((void**)&gl,   g_gl);

    // per stage: (2*64*72 + 2*BN*72)*2 bytes; two stages
    const int SMEM128 = 2 * (2 * 64 * 72 + 2 * 128 * 72) * 2;  // 110592
    const int SMEM64  = 2 * (2 * 64 * 72 + 2 * 64 * 72) * 2;   // 73728
    cudaFuncSetAttribute((gemm_mma<128, 0>), cudaFuncAttributeMaxDynamicSharedMemorySize, SMEM128);
    cudaFuncSetAttribute((gemm_mma<64, 0>),  cudaFuncAttributeMaxDynamicSharedMemorySize, SMEM64);
    cudaFuncSetAttribute((gemm_mma<128, 1>), cudaFuncAttributeMaxDynamicSharedMemorySize, SMEM128);

    const int tb = 256;
    int Emax = E1 > E2 ? E1 : E2;
    int mtiles = (n + 63) / 64;
    dim3 grid1(D1 / 128, mtiles);
    dim3 grid2(1, mtiles);
    int scat1Blocks = (int)(((size_t)E1 * 32 + tb - 1) / tb);
    int scat2Blocks = (int)(((size_t)E2 * 32 + tb - 1) / tb);
    int cvtItems = NW_ITEMS + n * 128;

    // 0-1: degree counts (self loop included via init=1)
    deg_init<<<(n + tb - 1) / tb, tb>>>(dg1, dg2, n);
    deg_count<<<(Emax + tb - 1) / tb, tb>>>(e1, e2, dg1, dg2, E1, E2);

    // 2: all bf16 conversions
    convert_all<<<(cvtItems + tb - 1) / tb, tb>>>(W10, W20, W21, (const float4*)x,
                                                  w10h, w10l, w20h, w20l, w21h, w21l,
                                                  (uint2*)xh, (uint2*)xl, n * 128);

    // 3: GEMM1 (profiled slot): H = (x@W10)*dinv1
    gemm_mma<128, 0><<<grid1, tb, SMEM128>>>(xh, xl, w10h, w10l, H, dg1, n, D1, F_IN);

    // 4: zero all scatter targets
    zero_all<<<(n * 96 + tb - 1) / tb, tb>>>((float4*)T1, (float4*)T2a, (float4*)T3, n);

    // 5-6: layer 1 propagate + epilogue (relu)  -> T1 = h1
    scatter_d256<<<scat1Blocks, tb>>>(H, T1, e1, E1);
    epi_d256<<<(n * 64 + tb - 1) / tb, tb>>>(T1, H, dg1, b10, n);

    // 7-9: layer 2: H2a = (x@W20)*dinv2 ; propagate ; s = (h2a)*dinv2 in place
    gemm_mma<64, 0><<<grid2, tb, SMEM64>>>(xh, xl, w20h, w20l, H2a, dg2, n, D2, F_IN);
    scatter_d64<<<scat2Blocks, tb>>>(H2a, T2a, e2, E2);
    epi_s<<<(n * 16 + tb - 1) / tb, tb>>>(T2a, H2a, dg2, b20, n);

    // 10-11: layer 3 propagation at 64 dims: T3 += s[src] ; G = (T3+s)*dinv2 -> bf16
    scatter_d64<<<scat2Blocks, tb>>>(H2a, T3, e2, E2);
    epi_emitG<<<(n * 16 + tb - 1) / tb, tb>>>(T3, H2a, dg2, (uint2*)gh, (uint2*)gl, n);

    // 12: GEMM3 with fused bias+relu: T2b = relu(G@W21 + b21) = h2
    gemm_mma<128, 1><<<grid1, tb, SMEM128>>>(gh, gl, w21h, w21l, T2b, b21, n, D1, D2);

    // 13: final dense
    final_fc<<<(n + 7) / 8, tb>>>(T1, T2b, Wfc, bfc, out, n);
}